// round 1
// baseline (speedup 1.0000x reference)
#include <cuda_runtime.h>
#include <math.h>

#define Bsz   32
#define Nn    4096
#define DIN   768
#define DS    256
#define KSL   8
#define DH    128
#define NITER 3
#define MROWS (Bsz*Nn)   // 131072

// ------------------------- scratch (device globals, no allocs) -------------
__device__ float g_pool_part[Bsz*8*DIN];
__device__ float g_pool[Bsz*DIN];
__device__ float g_t1[Bsz*512];
__device__ float g_slots[Bsz*KSL*DS];
__device__ float g_inputs[MROWS*DS];      // 134 MB
__device__ float g_kcat[MROWS*DS];        // 134 MB
__device__ float g_qcat[Bsz*KSL*DS];
__device__ float g_attn[Bsz*KSL*Nn];
__device__ float g_rowsum_part[Bsz*KSL*128];
__device__ float g_upd_part[Bsz*16*KSL*DS];

__device__ __forceinline__ float gelu_exact(float x) {
    return 0.5f * x * (1.0f + erff(x * 0.70710678118654752f));
}
__device__ __forceinline__ float sigmoidf_(float x) {
    return 1.0f / (1.0f + expf(-x));
}

// ------------------------- 1) feature pooling ------------------------------
// grid (3, 8, 32): dchunk, nchunk, b
__global__ void pool_part_kernel(const float* __restrict__ feat) {
    int d  = blockIdx.x * 256 + threadIdx.x;   // < 768
    int nc = blockIdx.y;
    int b  = blockIdx.z;
    float s = 0.f;
    const float* p = feat + (size_t)(b * Nn + nc * 512) * DIN + d;
    for (int n = 0; n < 512; ++n) s += p[(size_t)n * DIN];
    g_pool_part[(b * 8 + nc) * DIN + d] = s;
}
// grid (3, 32)
__global__ void pool_reduce_kernel() {
    int d = blockIdx.x * 256 + threadIdx.x;
    int b = blockIdx.y;
    float s = 0.f;
    for (int i = 0; i < 8; ++i) s += g_pool_part[(b * 8 + i) * DIN + d];
    g_pool[b * DIN + d] = s * (1.0f / (float)Nn);
}

// ------------------------- 2) slot init MLP --------------------------------
// grid (2, 32): jchunk, b
__global__ void slots_init1_kernel(const float* __restrict__ Wi1,
                                   const float* __restrict__ bi1) {
    __shared__ float s_pool[DIN];
    int t = threadIdx.x;
    int b = blockIdx.y;
    int j = blockIdx.x * 256 + t;              // < 512
    for (int i = t; i < DIN; i += 256) s_pool[i] = g_pool[b * DIN + i];
    __syncthreads();
    float acc = bi1[j];
    for (int k = 0; k < DIN; ++k) acc += s_pool[k] * Wi1[k * 512 + j];
    g_t1[b * 512 + j] = gelu_exact(acc);
}
// grid (8, 32): jchunk, b
__global__ void slots_init2_kernel(const float* __restrict__ Wi2,
                                   const float* __restrict__ bi2) {
    __shared__ float s_t[512];
    int t = threadIdx.x;
    int b = blockIdx.y;
    int j = blockIdx.x * 256 + t;              // < 2048
    s_t[t] = g_t1[b * 512 + t];
    s_t[t + 256] = g_t1[b * 512 + t + 256];
    __syncthreads();
    float acc = bi2[j];
    for (int k = 0; k < 512; ++k) acc += s_t[k] * Wi2[k * 2048 + j];
    g_slots[b * 2048 + j] = acc;
}

// ------------------------- 3) fused inputs = LN(feat @ Wp + bp) ------------
// BM=64, BN=256 (full row), BK=32. 256 threads, 8x8 microtile.
// warp w owns rows w*8..w*8+7 entirely -> LN via warp shuffles.
__global__ void __launch_bounds__(256)
gemm_ln_kernel(const float* __restrict__ feat, const float* __restrict__ Wp,
               const float* __restrict__ bp, const float* __restrict__ lng,
               const float* __restrict__ lnb) {
    __shared__ float As[64][36];
    __shared__ float Bs[32][260];
    int t  = threadIdx.x;
    int tx = t & 31, ty = t >> 5;
    int bRow = blockIdx.x * 64;

    float acc[8][8];
#pragma unroll
    for (int i = 0; i < 8; ++i)
#pragma unroll
        for (int j = 0; j < 8; ++j) acc[i][j] = 0.f;

    for (int k0 = 0; k0 < DIN; k0 += 32) {
#pragma unroll
        for (int i = 0; i < 2; ++i) {
            int idx = t + 256 * i;            // 0..511
            int row = idx >> 3, kq = idx & 7;
            float4 v = *reinterpret_cast<const float4*>(
                &feat[(size_t)(bRow + row) * DIN + k0 + kq * 4]);
            *reinterpret_cast<float4*>(&As[row][kq * 4]) = v;
        }
#pragma unroll
        for (int i = 0; i < 8; ++i) {
            int idx = t + 256 * i;            // 0..2047
            int kk = idx >> 6, cq = idx & 63;
            float4 v = *reinterpret_cast<const float4*>(&Wp[(k0 + kk) * 256 + cq * 4]);
            *reinterpret_cast<float4*>(&Bs[kk][cq * 4]) = v;
        }
        __syncthreads();
#pragma unroll 8
        for (int kk = 0; kk < 32; ++kk) {
            float4 b0 = *reinterpret_cast<const float4*>(&Bs[kk][tx * 4]);
            float4 b1 = *reinterpret_cast<const float4*>(&Bs[kk][128 + tx * 4]);
#pragma unroll
            for (int i = 0; i < 8; ++i) {
                float a = As[ty * 8 + i][kk];
                acc[i][0] += a * b0.x; acc[i][1] += a * b0.y;
                acc[i][2] += a * b0.z; acc[i][3] += a * b0.w;
                acc[i][4] += a * b1.x; acc[i][5] += a * b1.y;
                acc[i][6] += a * b1.z; acc[i][7] += a * b1.w;
            }
        }
        __syncthreads();
    }

    // bias + LN params for this thread's 8 columns
    float4 bp0 = *reinterpret_cast<const float4*>(&bp[tx * 4]);
    float4 bp1 = *reinterpret_cast<const float4*>(&bp[128 + tx * 4]);
    float4 gv0 = *reinterpret_cast<const float4*>(&lng[tx * 4]);
    float4 gv1 = *reinterpret_cast<const float4*>(&lng[128 + tx * 4]);
    float4 bv0 = *reinterpret_cast<const float4*>(&lnb[tx * 4]);
    float4 bv1 = *reinterpret_cast<const float4*>(&lnb[128 + tx * 4]);

#pragma unroll
    for (int i = 0; i < 8; ++i) {
        acc[i][0] += bp0.x; acc[i][1] += bp0.y; acc[i][2] += bp0.z; acc[i][3] += bp0.w;
        acc[i][4] += bp1.x; acc[i][5] += bp1.y; acc[i][6] += bp1.z; acc[i][7] += bp1.w;
        float s = 0.f, s2 = 0.f;
#pragma unroll
        for (int j = 0; j < 8; ++j) { s += acc[i][j]; s2 += acc[i][j] * acc[i][j]; }
#pragma unroll
        for (int o = 16; o > 0; o >>= 1) {
            s  += __shfl_xor_sync(0xffffffffu, s, o);
            s2 += __shfl_xor_sync(0xffffffffu, s2, o);
        }
        float m   = s * (1.0f / 256.0f);
        float var = s2 * (1.0f / 256.0f) - m * m;
        float inv = rsqrtf(var + 1e-5f);
        float4 o0, o1;
        o0.x = (acc[i][0] - m) * inv * gv0.x + bv0.x;
        o0.y = (acc[i][1] - m) * inv * gv0.y + bv0.y;
        o0.z = (acc[i][2] - m) * inv * gv0.z + bv0.z;
        o0.w = (acc[i][3] - m) * inv * gv0.w + bv0.w;
        o1.x = (acc[i][4] - m) * inv * gv1.x + bv1.x;
        o1.y = (acc[i][5] - m) * inv * gv1.y + bv1.y;
        o1.z = (acc[i][6] - m) * inv * gv1.z + bv1.z;
        o1.w = (acc[i][7] - m) * inv * gv1.w + bv1.w;
        size_t row = (size_t)(bRow + ty * 8 + i);
        *reinterpret_cast<float4*>(&g_inputs[row * 256 + tx * 4])       = o0;
        *reinterpret_cast<float4*>(&g_inputs[row * 256 + 128 + tx * 4]) = o1;
    }
}

// ------------------------- 4) k_cat = [inp_s@Wks | inp_t@Wkt] ---------------
// grid (2048, 2). BM=64, BN=128, BK=32.
__global__ void __launch_bounds__(256)
kproj_kernel(const float* __restrict__ Wks, const float* __restrict__ Wkt) {
    __shared__ float As[64][36];
    __shared__ float Bs[32][132];
    int t  = threadIdx.x;
    int tx = t & 31, ty = t >> 5;
    int bRow = blockIdx.x * 64;
    int z = blockIdx.y;
    const float* W = z ? Wkt : Wks;

    float acc[8][4];
#pragma unroll
    for (int i = 0; i < 8; ++i)
#pragma unroll
        for (int j = 0; j < 4; ++j) acc[i][j] = 0.f;

    for (int k0 = 0; k0 < 128; k0 += 32) {
#pragma unroll
        for (int i = 0; i < 2; ++i) {
            int idx = t + 256 * i;
            int row = idx >> 3, kq = idx & 7;
            float4 v = *reinterpret_cast<const float4*>(
                &g_inputs[(size_t)(bRow + row) * 256 + z * 128 + k0 + kq * 4]);
            *reinterpret_cast<float4*>(&As[row][kq * 4]) = v;
        }
#pragma unroll
        for (int i = 0; i < 4; ++i) {
            int idx = t + 256 * i;
            int kk = idx >> 5, cq = idx & 31;
            float4 v = *reinterpret_cast<const float4*>(&W[(k0 + kk) * 128 + cq * 4]);
            *reinterpret_cast<float4*>(&Bs[kk][cq * 4]) = v;
        }
        __syncthreads();
#pragma unroll 8
        for (int kk = 0; kk < 32; ++kk) {
            float4 bv = *reinterpret_cast<const float4*>(&Bs[kk][tx * 4]);
#pragma unroll
            for (int i = 0; i < 8; ++i) {
                float a = As[ty * 8 + i][kk];
                acc[i][0] += a * bv.x; acc[i][1] += a * bv.y;
                acc[i][2] += a * bv.z; acc[i][3] += a * bv.w;
            }
        }
        __syncthreads();
    }
#pragma unroll
    for (int i = 0; i < 8; ++i) {
        size_t row = (size_t)(bRow + ty * 8 + i);
        *reinterpret_cast<float4*>(&g_kcat[row * 256 + z * 128 + tx * 4]) =
            make_float4(acc[i][0], acc[i][1], acc[i][2], acc[i][3]);
    }
}

// ------------------------- 5) q projection (scales prefolded) --------------
// grid (32, 8): b, kslot
__global__ void qproj_kernel(const float* __restrict__ Wqs,
                             const float* __restrict__ Wqt) {
    __shared__ float s_slot[256];
    int t = threadIdx.x;
    int b = blockIdx.x, ks = blockIdx.y;
    s_slot[t] = g_slots[(b * KSL + ks) * 256 + t];
    __syncthreads();
    int half = t >> 7;
    int cc   = t & 127;
    const float* W = half ? Wqt : Wqs;
    const float rs = 0.08838834764831845f;    // 128^-0.5
    float sc = half ? 0.3f * rs : 0.7f * rs;
    float acc = 0.f;
    const float* sp = &s_slot[half * 128];
#pragma unroll 8
    for (int j = 0; j < 128; ++j) acc += sp[j] * W[j * 128 + cc];
    g_qcat[(b * KSL + ks) * 256 + t] = acc * sc;
}

// ------------------------- 6) logits + softmax(K) + rowsum partials --------
// grid (128, 32): nchunk(32 n each), b. 256 threads: kk = t>>5, nl = t&31.
__global__ void __launch_bounds__(256)
logits_softmax_kernel() {
    __shared__ float s_q[8 * 256];
    __shared__ float s_k[32 * 257];
    __shared__ float s_m[32], s_e[32];
    __shared__ float s_a[8][32];
    int t  = threadIdx.x;
    int nc = blockIdx.x, b = blockIdx.y;

#pragma unroll
    for (int i = 0; i < 8; ++i) s_q[t + 256 * i] = g_qcat[b * 2048 + t + 256 * i];
#pragma unroll
    for (int i = 0; i < 8; ++i) {
        int idx = t + 256 * i;                  // float4 units, 0..2047
        int n = idx >> 6, dq = idx & 63;
        float4 v = *reinterpret_cast<const float4*>(
            &g_kcat[(size_t)(b * Nn + nc * 32 + n) * 256 + dq * 4]);
        float* dst = &s_k[n * 257 + dq * 4];
        dst[0] = v.x; dst[1] = v.y; dst[2] = v.z; dst[3] = v.w;
    }
    __syncthreads();

    int kk = t >> 5, nl = t & 31;
    const float* qp = &s_q[kk * 256];
    const float* kp = &s_k[nl * 257];
    float acc = 0.f;
#pragma unroll 8
    for (int d = 0; d < 256; ++d) acc += qp[d] * kp[d];
    s_a[kk][nl] = acc;
    __syncthreads();

    if (kk == 0) {  // 32 threads, one per n
        float m = -1e30f;
#pragma unroll
        for (int i = 0; i < 8; ++i) m = fmaxf(m, s_a[i][nl]);
        float e = 0.f;
#pragma unroll
        for (int i = 0; i < 8; ++i) e += expf(s_a[i][nl] - m);
        s_m[nl] = m; s_e[nl] = e;
    }
    __syncthreads();

    float a = expf(acc - s_m[nl]) / s_e[nl];
    g_attn[(size_t)(b * KSL + kk) * Nn + nc * 32 + nl] = a;
    s_a[kk][nl] = a;
    __syncthreads();

    if (nl == 0) {
        float s = 0.f;
#pragma unroll
        for (int i = 0; i < 32; ++i) s += s_a[kk][i];
        g_rowsum_part[(b * KSL + kk) * 128 + nc] = s;
    }
}

// ------------------------- 7) updates stage 1 (partials over n) ------------
// grid (16, 32): nchunk(256 n each), b. 256 threads: t = d.
__global__ void __launch_bounds__(256)
upd1_kernel() {
    __shared__ float s_a[8][256];
    int t  = threadIdx.x;
    int nc = blockIdx.x, b = blockIdx.y;
#pragma unroll
    for (int i = 0; i < 8; ++i) {
        int idx = t + 256 * i;
        int kk = idx >> 8, nl = idx & 255;
        s_a[kk][nl] = g_attn[(size_t)(b * KSL + kk) * Nn + nc * 256 + nl];
    }
    __syncthreads();
    float acc[8] = {0, 0, 0, 0, 0, 0, 0, 0};
    const float* ip = &g_inputs[(size_t)(b * Nn + nc * 256) * 256 + t];
#pragma unroll 4
    for (int nl = 0; nl < 256; ++nl) {
        float inp = ip[(size_t)nl * 256];
#pragma unroll
        for (int kk = 0; kk < 8; ++kk) acc[kk] += s_a[kk][nl] * inp;
    }
#pragma unroll
    for (int kk = 0; kk < 8; ++kk)
        g_upd_part[((b * 16 + nc) * 8 + kk) * 256 + t] = acc[kk];
}

// ------------------------- 8) fused finalize + GRU + LN + MLP --------------
// grid (8, 32): kslot, b. 256 threads: t = j.
__global__ void __launch_bounds__(256)
gru_mlp_kernel(const float* __restrict__ W_ih, const float* __restrict__ W_hh,
               const float* __restrict__ b_ih, const float* __restrict__ b_hh,
               const float* __restrict__ lng, const float* __restrict__ lnb,
               const float* __restrict__ Wm1, const float* __restrict__ bm1,
               const float* __restrict__ Wm2, const float* __restrict__ bm2) {
    __shared__ float s_x[256], s_h[256], s_t2[512];
    __shared__ float wred[8], wred2[8];
    __shared__ float s_rs;
    int t  = threadIdx.x;
    int ks = blockIdx.x, b = blockIdx.y;
    int lane = t & 31, w = t >> 5;

    // rowsum reduce (128 partials)
    float v = (t < 128) ? g_rowsum_part[(b * KSL + ks) * 128 + t] : 0.f;
#pragma unroll
    for (int o = 16; o > 0; o >>= 1) v += __shfl_xor_sync(0xffffffffu, v, o);
    if (lane == 0) wred[w] = v;
    __syncthreads();
    if (t == 0) {
        float s = 0.f;
        for (int i = 0; i < 8; ++i) s += wred[i];
        s_rs = s;
    }
    __syncthreads();
    float inv_rs = 1.0f / (s_rs + 1e-8f);

    float u = 0.f;
#pragma unroll
    for (int ncp = 0; ncp < 16; ++ncp)
        u += g_upd_part[((b * 16 + ncp) * 8 + ks) * 256 + t];
    u *= inv_rs;
    s_x[t] = u;
    float hprev = g_slots[(b * KSL + ks) * 256 + t];
    s_h[t] = hprev;
    __syncthreads();

    // GRU gates
    float gx0 = b_ih[t], gx1 = b_ih[t + 256], gx2 = b_ih[t + 512];
    float gh0 = b_hh[t], gh1 = b_hh[t + 256], gh2 = b_hh[t + 512];
#pragma unroll 4
    for (int m = 0; m < 256; ++m) {
        float xm = s_x[m], hm = s_h[m];
        const float* wi = &W_ih[m * 768];
        const float* wh = &W_hh[m * 768];
        gx0 += xm * wi[t]; gx1 += xm * wi[t + 256]; gx2 += xm * wi[t + 512];
        gh0 += hm * wh[t]; gh1 += hm * wh[t + 256]; gh2 += hm * wh[t + 512];
    }
    float r = sigmoidf_(gx0 + gh0);
    float z = sigmoidf_(gx1 + gh1);
    float n = tanhf(gx2 + r * gh2);
    float h = (1.0f - z) * n + z * hprev;

    // LN(h) across 256
    float s1 = h, s2 = h * h;
#pragma unroll
    for (int o = 16; o > 0; o >>= 1) {
        s1 += __shfl_xor_sync(0xffffffffu, s1, o);
        s2 += __shfl_xor_sync(0xffffffffu, s2, o);
    }
    __syncthreads();            // done with s_x reads of GRU loop
    if (lane == 0) { wred[w] = s1; wred2[w] = s2; }
    __syncthreads();
    float S = 0.f, S2 = 0.f;
#pragma unroll
    for (int i = 0; i < 8; ++i) { S += wred[i]; S2 += wred2[i]; }
    float mean = S * (1.0f / 256.0f);
    float var  = S2 * (1.0f / 256.0f) - mean * mean;
    float sn = (h - mean) * rsqrtf(var + 1e-5f) * lng[t] + lnb[t];
    s_x[t] = sn;
    __syncthreads();

    // MLP: gelu(sn @ Wm1 + bm1) @ Wm2 + bm2
    float m0 = bm1[t], m1 = bm1[t + 256];
#pragma unroll 4
    for (int j = 0; j < 256; ++j) {
        float s = s_x[j];
        m0 += s * Wm1[j * 512 + t];
        m1 += s * Wm1[j * 512 + t + 256];
    }
    s_t2[t]       = gelu_exact(m0);
    s_t2[t + 256] = gelu_exact(m1);
    __syncthreads();
    float out = bm2[t];
#pragma unroll 4
    for (int j = 0; j < 512; ++j) out += s_t2[j] * Wm2[j * 256 + t];
    g_slots[(b * KSL + ks) * 256 + t] = h + out;
}

// ------------------------- 9) pack outputs ---------------------------------
__global__ void writeout_kernel(float* __restrict__ out) {
    int i = blockIdx.x * 256 + threadIdx.x;   // < 1179648
    const int SZ_SLOTS = Bsz * KSL * DS;      // 65536
    const int SZ_ATTN  = Bsz * KSL * Nn;      // 1048576
    const int SZ_HALF  = Bsz * KSL * DH;      // 32768
    if (i < SZ_SLOTS) {
        out[i] = g_slots[i];
    } else if (i < SZ_SLOTS + SZ_ATTN) {
        out[i] = g_attn[i - SZ_SLOTS];
    } else if (i < SZ_SLOTS + SZ_ATTN + SZ_HALF) {
        int j = i - SZ_SLOTS - SZ_ATTN;
        int bk = j >> 7, d = j & 127;
        out[i] = g_slots[bk * 256 + d];
    } else if (i < SZ_SLOTS + SZ_ATTN + 2 * SZ_HALF) {
        int j = i - SZ_SLOTS - SZ_ATTN - SZ_HALF;
        int bk = j >> 7, d = j & 127;
        out[i] = g_slots[bk * 256 + 128 + d];
    }
}

// ------------------------- launch ------------------------------------------
extern "C" void kernel_launch(void* const* d_in, const int* in_sizes, int n_in,
                              void* d_out, int out_size) {
    const float* features = (const float*)d_in[0];
    const float* Wi1  = (const float*)d_in[1];
    const float* bi1  = (const float*)d_in[2];
    const float* Wi2  = (const float*)d_in[3];
    const float* bi2  = (const float*)d_in[4];
    const float* Wp   = (const float*)d_in[5];
    const float* bp   = (const float*)d_in[6];
    const float* ln_in_g = (const float*)d_in[7];
    const float* ln_in_b = (const float*)d_in[8];
    const float* Wqs  = (const float*)d_in[9];
    const float* Wks  = (const float*)d_in[10];
    const float* Wqt  = (const float*)d_in[11];
    const float* Wkt  = (const float*)d_in[12];
    const float* W_ih = (const float*)d_in[13];
    const float* W_hh = (const float*)d_in[14];
    const float* b_ih = (const float*)d_in[15];
    const float* b_hh = (const float*)d_in[16];
    const float* ln_g = (const float*)d_in[17];
    const float* ln_b = (const float*)d_in[18];
    const float* Wm1  = (const float*)d_in[19];
    const float* bm1  = (const float*)d_in[20];
    const float* Wm2  = (const float*)d_in[21];
    const float* bm2  = (const float*)d_in[22];
    float* out = (float*)d_out;

    pool_part_kernel<<<dim3(3, 8, 32), 256>>>(features);
    pool_reduce_kernel<<<dim3(3, 32), 256>>>();
    slots_init1_kernel<<<dim3(2, 32), 256>>>(Wi1, bi1);
    slots_init2_kernel<<<dim3(8, 32), 256>>>(Wi2, bi2);
    gemm_ln_kernel<<<2048, 256>>>(features, Wp, bp, ln_in_g, ln_in_b);
    kproj_kernel<<<dim3(2048, 2), 256>>>(Wks, Wkt);

    for (int it = 0; it < NITER; ++it) {
        qproj_kernel<<<dim3(32, 8), 256>>>(Wqs, Wqt);
        logits_softmax_kernel<<<dim3(128, 32), 256>>>();
        upd1_kernel<<<dim3(16, 32), 256>>>();
        gru_mlp_kernel<<<dim3(8, 32), 256>>>(W_ih, W_hh, b_ih, b_hh,
                                             ln_g, ln_b, Wm1, bm1, Wm2, bm2);
    }
    writeout_kernel<<<4608, 256>>>(out);
}

// round 2
// speedup vs baseline: 1.4952x; 1.4952x over previous
#include <cuda_runtime.h>
#include <math.h>
#include <stdint.h>

#define Bsz   32
#define Nn    4096
#define DIN   768
#define DS    256
#define KSL   8
#define DH    128
#define NITER 3
#define MROWS (Bsz*Nn)   // 131072

// ------------------------- scratch (device globals, no allocs) -------------
__device__ float g_pool_part[Bsz*8*DIN];
__device__ float g_pool[Bsz*DIN];
__device__ float g_t1[Bsz*512];
__device__ float g_slots[Bsz*KSL*DS];
__device__ float g_inputs[MROWS*DS];      // 134 MB
__device__ float g_kcat[MROWS*DS];        // 134 MB
__device__ float g_qcat[Bsz*KSL*DS];
__device__ float g_attn[Bsz*KSL*Nn];
__device__ float g_rowsum_part[Bsz*KSL*128];
__device__ float g_upd_part[Bsz*16*KSL*DS];

__device__ __forceinline__ float gelu_exact(float x) {
    return 0.5f * x * (1.0f + erff(x * 0.70710678118654752f));
}
__device__ __forceinline__ float sigmoidf_(float x) {
    return 1.0f / (1.0f + expf(-x));
}
__device__ __forceinline__ uint32_t f2tf(float f) {
    uint32_t u;
    asm("cvt.rna.tf32.f32 %0, %1;" : "=r"(u) : "f"(f));
    return u;
}
__device__ __forceinline__ void mma_tf32(float* c, const uint32_t* a,
                                         uint32_t b0, uint32_t b1) {
    asm volatile(
        "mma.sync.aligned.m16n8k8.row.col.f32.tf32.tf32.f32 "
        "{%0,%1,%2,%3}, {%4,%5,%6,%7}, {%8,%9}, {%0,%1,%2,%3};\n"
        : "+f"(c[0]), "+f"(c[1]), "+f"(c[2]), "+f"(c[3])
        : "r"(a[0]), "r"(a[1]), "r"(a[2]), "r"(a[3]), "r"(b0), "r"(b1));
}

// ------------------------- 1) feature pooling ------------------------------
__global__ void pool_part_kernel(const float* __restrict__ feat) {
    int d  = blockIdx.x * 256 + threadIdx.x;   // < 768
    int nc = blockIdx.y;
    int b  = blockIdx.z;
    float s = 0.f;
    const float* p = feat + (size_t)(b * Nn + nc * 512) * DIN + d;
    for (int n = 0; n < 512; ++n) s += p[(size_t)n * DIN];
    g_pool_part[(b * 8 + nc) * DIN + d] = s;
}
__global__ void pool_reduce_kernel() {
    int d = blockIdx.x * 256 + threadIdx.x;
    int b = blockIdx.y;
    float s = 0.f;
    for (int i = 0; i < 8; ++i) s += g_pool_part[(b * 8 + i) * DIN + d];
    g_pool[b * DIN + d] = s * (1.0f / (float)Nn);
}

// ------------------------- 2) slot init MLP --------------------------------
__global__ void slots_init1_kernel(const float* __restrict__ Wi1,
                                   const float* __restrict__ bi1) {
    __shared__ float s_pool[DIN];
    int t = threadIdx.x;
    int b = blockIdx.y;
    int j = blockIdx.x * 256 + t;              // < 512
    for (int i = t; i < DIN; i += 256) s_pool[i] = g_pool[b * DIN + i];
    __syncthreads();
    float acc = bi1[j];
    for (int k = 0; k < DIN; ++k) acc += s_pool[k] * Wi1[k * 512 + j];
    g_t1[b * 512 + j] = gelu_exact(acc);
}
__global__ void slots_init2_kernel(const float* __restrict__ Wi2,
                                   const float* __restrict__ bi2) {
    __shared__ float s_t[512];
    int t = threadIdx.x;
    int b = blockIdx.y;
    int j = blockIdx.x * 256 + t;              // < 2048
    s_t[t] = g_t1[b * 512 + t];
    s_t[t + 256] = g_t1[b * 512 + t + 256];
    __syncthreads();
    float acc = bi2[j];
    for (int k = 0; k < 512; ++k) acc += s_t[k] * Wi2[k * 2048 + j];
    g_slots[b * 2048 + j] = acc;
}

// ------------------------- 3) tf32 TC GEMM + fused LN ----------------------
// inputs = LN(feat @ Wp + bp). BM=64, BN=256, BK=32. 8 warps (2x4 grid),
// warp tile 32x64 via m16n8k8 tf32 (2 m-tiles x 8 n-tiles).
__global__ void __launch_bounds__(256)
gemm_ln_tc(const float* __restrict__ feat, const float* __restrict__ Wp,
           const float* __restrict__ bp, const float* __restrict__ lng,
           const float* __restrict__ lnb) {
    __shared__ uint32_t As[64][36];     // pad 36 -> frag bank = 4r+c
    __shared__ uint32_t Bs2[32][264];   // pad 264 -> frag bank = 8k+n
    __shared__ float s_sum[64][4];
    __shared__ float s_sq[64][4];

    int t = threadIdx.x;
    int lane = t & 31, wid = t >> 5;
    int wr = wid >> 2, wc = wid & 3;    // warp row (0..1), warp col (0..3)
    int g = lane >> 2, tg = lane & 3;
    int bRow = blockIdx.x * 64;

    float c[2][8][4];
#pragma unroll
    for (int mt = 0; mt < 2; ++mt)
#pragma unroll
        for (int nt = 0; nt < 8; ++nt)
#pragma unroll
            for (int j = 0; j < 4; ++j) c[mt][nt][j] = 0.f;

    for (int k0 = 0; k0 < DIN; k0 += 32) {
#pragma unroll
        for (int i = 0; i < 2; ++i) {
            int idx = t + 256 * i;             // 0..511
            int row = idx >> 3, q = idx & 7;
            float4 v = *reinterpret_cast<const float4*>(
                &feat[(size_t)(bRow + row) * DIN + k0 + q * 4]);
            As[row][q * 4 + 0] = f2tf(v.x);
            As[row][q * 4 + 1] = f2tf(v.y);
            As[row][q * 4 + 2] = f2tf(v.z);
            As[row][q * 4 + 3] = f2tf(v.w);
        }
#pragma unroll
        for (int i = 0; i < 8; ++i) {
            int idx = t + 256 * i;             // 0..2047
            int kk = idx >> 6, cq = idx & 63;
            float4 v = *reinterpret_cast<const float4*>(
                &Wp[(size_t)(k0 + kk) * 256 + cq * 4]);
            Bs2[kk][cq * 4 + 0] = f2tf(v.x);
            Bs2[kk][cq * 4 + 1] = f2tf(v.y);
            Bs2[kk][cq * 4 + 2] = f2tf(v.z);
            Bs2[kk][cq * 4 + 3] = f2tf(v.w);
        }
        __syncthreads();
#pragma unroll
        for (int ks = 0; ks < 4; ++ks) {
            uint32_t a[2][4];
#pragma unroll
            for (int mt = 0; mt < 2; ++mt) {
                int r = wr * 32 + mt * 16 + g;
                a[mt][0] = As[r][ks * 8 + tg];
                a[mt][1] = As[r + 8][ks * 8 + tg];
                a[mt][2] = As[r][ks * 8 + tg + 4];
                a[mt][3] = As[r + 8][ks * 8 + tg + 4];
            }
#pragma unroll
            for (int nt = 0; nt < 8; ++nt) {
                int cb = wc * 64 + nt * 8 + g;
                uint32_t b0 = Bs2[ks * 8 + tg][cb];
                uint32_t b1 = Bs2[ks * 8 + tg + 4][cb];
                mma_tf32(c[0][nt], a[0], b0, b1);
                mma_tf32(c[1][nt], a[1], b0, b1);
            }
        }
        __syncthreads();
    }

    // --- epilogue: bias + LN over 256 cols, from register fragments ---
    float2 bpv[8], gv[8], bvv[8];
#pragma unroll
    for (int nt = 0; nt < 8; ++nt) {
        int cb = wc * 64 + nt * 8 + tg * 2;
        bpv[nt] = *reinterpret_cast<const float2*>(&bp[cb]);
        gv[nt]  = *reinterpret_cast<const float2*>(&lng[cb]);
        bvv[nt] = *reinterpret_cast<const float2*>(&lnb[cb]);
    }
    float ls[2][2], lq[2][2];
#pragma unroll
    for (int mt = 0; mt < 2; ++mt)
#pragma unroll
        for (int h = 0; h < 2; ++h) { ls[mt][h] = 0.f; lq[mt][h] = 0.f; }
#pragma unroll
    for (int mt = 0; mt < 2; ++mt)
#pragma unroll
        for (int nt = 0; nt < 8; ++nt) {
            c[mt][nt][0] += bpv[nt].x;
            c[mt][nt][1] += bpv[nt].y;
            c[mt][nt][2] += bpv[nt].x;
            c[mt][nt][3] += bpv[nt].y;
            ls[mt][0] += c[mt][nt][0] + c[mt][nt][1];
            lq[mt][0] += c[mt][nt][0] * c[mt][nt][0] + c[mt][nt][1] * c[mt][nt][1];
            ls[mt][1] += c[mt][nt][2] + c[mt][nt][3];
            lq[mt][1] += c[mt][nt][2] * c[mt][nt][2] + c[mt][nt][3] * c[mt][nt][3];
        }
    // reduce across the 4 lanes sharing the same row (lane%4 group)
#pragma unroll
    for (int mt = 0; mt < 2; ++mt)
#pragma unroll
        for (int h = 0; h < 2; ++h) {
            ls[mt][h] += __shfl_xor_sync(0xffffffffu, ls[mt][h], 1);
            ls[mt][h] += __shfl_xor_sync(0xffffffffu, ls[mt][h], 2);
            lq[mt][h] += __shfl_xor_sync(0xffffffffu, lq[mt][h], 1);
            lq[mt][h] += __shfl_xor_sync(0xffffffffu, lq[mt][h], 2);
        }
    if (tg == 0) {
#pragma unroll
        for (int mt = 0; mt < 2; ++mt)
#pragma unroll
            for (int h = 0; h < 2; ++h) {
                int rl = wr * 32 + mt * 16 + h * 8 + g;
                s_sum[rl][wc] = ls[mt][h];
                s_sq[rl][wc]  = lq[mt][h];
            }
    }
    __syncthreads();
    float mean[2][2], inv[2][2];
#pragma unroll
    for (int mt = 0; mt < 2; ++mt)
#pragma unroll
        for (int h = 0; h < 2; ++h) {
            int rl = wr * 32 + mt * 16 + h * 8 + g;
            float S = s_sum[rl][0] + s_sum[rl][1] + s_sum[rl][2] + s_sum[rl][3];
            float Q = s_sq[rl][0] + s_sq[rl][1] + s_sq[rl][2] + s_sq[rl][3];
            float m = S * (1.0f / 256.0f);
            float v = Q * (1.0f / 256.0f) - m * m;
            mean[mt][h] = m;
            inv[mt][h]  = rsqrtf(v + 1e-5f);
        }
#pragma unroll
    for (int mt = 0; mt < 2; ++mt)
#pragma unroll
        for (int nt = 0; nt < 8; ++nt)
#pragma unroll
            for (int h = 0; h < 2; ++h) {
                int rl = wr * 32 + mt * 16 + h * 8 + g;
                size_t row = (size_t)(bRow + rl);
                int cb = wc * 64 + nt * 8 + tg * 2;
                float2 o;
                o.x = (c[mt][nt][h * 2]     - mean[mt][h]) * inv[mt][h] * gv[nt].x + bvv[nt].x;
                o.y = (c[mt][nt][h * 2 + 1] - mean[mt][h]) * inv[mt][h] * gv[nt].y + bvv[nt].y;
                *reinterpret_cast<float2*>(&g_inputs[row * 256 + cb]) = o;
            }
}

// ------------------------- 4) tf32 TC k-projection -------------------------
// k_cat = [inp_s@Wks | inp_t@Wkt]. grid (2048, 2). BM=64, BN=128, BK=32.
// 8 warps (2x4), warp tile 32x32 (2 m-tiles x 4 n-tiles).
__global__ void __launch_bounds__(256)
kproj_tc(const float* __restrict__ Wks, const float* __restrict__ Wkt) {
    __shared__ uint32_t As[64][36];
    __shared__ uint32_t Bs2[32][136];

    int t = threadIdx.x;
    int lane = t & 31, wid = t >> 5;
    int wr = wid >> 2, wc = wid & 3;
    int g = lane >> 2, tg = lane & 3;
    int bRow = blockIdx.x * 64;
    int z = blockIdx.y;
    const float* W = z ? Wkt : Wks;

    float c[2][4][4];
#pragma unroll
    for (int mt = 0; mt < 2; ++mt)
#pragma unroll
        for (int nt = 0; nt < 4; ++nt)
#pragma unroll
            for (int j = 0; j < 4; ++j) c[mt][nt][j] = 0.f;

    for (int k0 = 0; k0 < 128; k0 += 32) {
#pragma unroll
        for (int i = 0; i < 2; ++i) {
            int idx = t + 256 * i;
            int row = idx >> 3, q = idx & 7;
            float4 v = *reinterpret_cast<const float4*>(
                &g_inputs[(size_t)(bRow + row) * 256 + z * 128 + k0 + q * 4]);
            As[row][q * 4 + 0] = f2tf(v.x);
            As[row][q * 4 + 1] = f2tf(v.y);
            As[row][q * 4 + 2] = f2tf(v.z);
            As[row][q * 4 + 3] = f2tf(v.w);
        }
#pragma unroll
        for (int i = 0; i < 4; ++i) {
            int idx = t + 256 * i;             // 0..1023
            int kk = idx >> 5, cq = idx & 31;
            float4 v = *reinterpret_cast<const float4*>(
                &W[(size_t)(k0 + kk) * 128 + cq * 4]);
            Bs2[kk][cq * 4 + 0] = f2tf(v.x);
            Bs2[kk][cq * 4 + 1] = f2tf(v.y);
            Bs2[kk][cq * 4 + 2] = f2tf(v.z);
            Bs2[kk][cq * 4 + 3] = f2tf(v.w);
        }
        __syncthreads();
#pragma unroll
        for (int ks = 0; ks < 4; ++ks) {
            uint32_t a[2][4];
#pragma unroll
            for (int mt = 0; mt < 2; ++mt) {
                int r = wr * 32 + mt * 16 + g;
                a[mt][0] = As[r][ks * 8 + tg];
                a[mt][1] = As[r + 8][ks * 8 + tg];
                a[mt][2] = As[r][ks * 8 + tg + 4];
                a[mt][3] = As[r + 8][ks * 8 + tg + 4];
            }
#pragma unroll
            for (int nt = 0; nt < 4; ++nt) {
                int cb = wc * 32 + nt * 8 + g;
                uint32_t b0 = Bs2[ks * 8 + tg][cb];
                uint32_t b1 = Bs2[ks * 8 + tg + 4][cb];
                mma_tf32(c[0][nt], a[0], b0, b1);
                mma_tf32(c[1][nt], a[1], b0, b1);
            }
        }
        __syncthreads();
    }
#pragma unroll
    for (int mt = 0; mt < 2; ++mt)
#pragma unroll
        for (int nt = 0; nt < 4; ++nt)
#pragma unroll
            for (int h = 0; h < 2; ++h) {
                int rl = wr * 32 + mt * 16 + h * 8 + g;
                size_t row = (size_t)(bRow + rl);
                int cb = wc * 32 + nt * 8 + tg * 2;
                float2 o;
                o.x = c[mt][nt][h * 2];
                o.y = c[mt][nt][h * 2 + 1];
                *reinterpret_cast<float2*>(&g_kcat[row * 256 + z * 128 + cb]) = o;
            }
}

// ------------------------- 5) q projection (scales prefolded) --------------
__global__ void qproj_kernel(const float* __restrict__ Wqs,
                             const float* __restrict__ Wqt) {
    __shared__ float s_slot[256];
    int t = threadIdx.x;
    int b = blockIdx.x, ks = blockIdx.y;
    s_slot[t] = g_slots[(b * KSL + ks) * 256 + t];
    __syncthreads();
    int half = t >> 7;
    int cc   = t & 127;
    const float* W = half ? Wqt : Wqs;
    const float rs = 0.08838834764831845f;    // 128^-0.5
    float sc = half ? 0.3f * rs : 0.7f * rs;
    float acc = 0.f;
    const float* sp = &s_slot[half * 128];
#pragma unroll 8
    for (int j = 0; j < 128; ++j) acc += sp[j] * W[j * 128 + cc];
    g_qcat[(b * KSL + ks) * 256 + t] = acc * sc;
}

// ------------------------- 6) logits + softmax(K) + rowsum partials --------
__global__ void __launch_bounds__(256)
logits_softmax_kernel() {
    __shared__ float s_q[8 * 256];
    __shared__ float s_k[32 * 257];
    __shared__ float s_m[32], s_e[32];
    __shared__ float s_a[8][32];
    int t  = threadIdx.x;
    int nc = blockIdx.x, b = blockIdx.y;

#pragma unroll
    for (int i = 0; i < 8; ++i) s_q[t + 256 * i] = g_qcat[b * 2048 + t + 256 * i];
#pragma unroll
    for (int i = 0; i < 8; ++i) {
        int idx = t + 256 * i;                  // float4 units, 0..2047
        int n = idx >> 6, dq = idx & 63;
        float4 v = *reinterpret_cast<const float4*>(
            &g_kcat[(size_t)(b * Nn + nc * 32 + n) * 256 + dq * 4]);
        float* dst = &s_k[n * 257 + dq * 4];
        dst[0] = v.x; dst[1] = v.y; dst[2] = v.z; dst[3] = v.w;
    }
    __syncthreads();

    int kk = t >> 5, nl = t & 31;
    const float* qp = &s_q[kk * 256];
    const float* kp = &s_k[nl * 257];
    float acc = 0.f;
#pragma unroll 8
    for (int d = 0; d < 256; ++d) acc += qp[d] * kp[d];
    s_a[kk][nl] = acc;
    __syncthreads();

    if (kk == 0) {
        float m = -1e30f;
#pragma unroll
        for (int i = 0; i < 8; ++i) m = fmaxf(m, s_a[i][nl]);
        float e = 0.f;
#pragma unroll
        for (int i = 0; i < 8; ++i) e += expf(s_a[i][nl] - m);
        s_m[nl] = m; s_e[nl] = e;
    }
    __syncthreads();

    float a = expf(acc - s_m[nl]) / s_e[nl];
    g_attn[(size_t)(b * KSL + kk) * Nn + nc * 32 + nl] = a;
    s_a[kk][nl] = a;
    __syncthreads();

    if (nl == 0) {
        float s = 0.f;
#pragma unroll
        for (int i = 0; i < 32; ++i) s += s_a[kk][i];
        g_rowsum_part[(b * KSL + kk) * 128 + nc] = s;
    }
}

// ------------------------- 7) updates stage 1 (partials over n) ------------
__global__ void __launch_bounds__(256)
upd1_kernel() {
    __shared__ float s_a[8][256];
    int t  = threadIdx.x;
    int nc = blockIdx.x, b = blockIdx.y;
#pragma unroll
    for (int i = 0; i < 8; ++i) {
        int idx = t + 256 * i;
        int kk = idx >> 8, nl = idx & 255;
        s_a[kk][nl] = g_attn[(size_t)(b * KSL + kk) * Nn + nc * 256 + nl];
    }
    __syncthreads();
    float acc[8] = {0, 0, 0, 0, 0, 0, 0, 0};
    const float* ip = &g_inputs[(size_t)(b * Nn + nc * 256) * 256 + t];
#pragma unroll 4
    for (int nl = 0; nl < 256; ++nl) {
        float inp = ip[(size_t)nl * 256];
#pragma unroll
        for (int kk = 0; kk < 8; ++kk) acc[kk] += s_a[kk][nl] * inp;
    }
#pragma unroll
    for (int kk = 0; kk < 8; ++kk)
        g_upd_part[((b * 16 + nc) * 8 + kk) * 256 + t] = acc[kk];
}

// ------------------------- 8) fused finalize + GRU + LN + MLP --------------
__global__ void __launch_bounds__(256)
gru_mlp_kernel(const float* __restrict__ W_ih, const float* __restrict__ W_hh,
               const float* __restrict__ b_ih, const float* __restrict__ b_hh,
               const float* __restrict__ lng, const float* __restrict__ lnb,
               const float* __restrict__ Wm1, const float* __restrict__ bm1,
               const float* __restrict__ Wm2, const float* __restrict__ bm2) {
    __shared__ float s_x[256], s_h[256], s_t2[512];
    __shared__ float wred[8], wred2[8];
    __shared__ float s_rs;
    int t  = threadIdx.x;
    int ks = blockIdx.x, b = blockIdx.y;
    int lane = t & 31, w = t >> 5;

    float v = (t < 128) ? g_rowsum_part[(b * KSL + ks) * 128 + t] : 0.f;
#pragma unroll
    for (int o = 16; o > 0; o >>= 1) v += __shfl_xor_sync(0xffffffffu, v, o);
    if (lane == 0) wred[w] = v;
    __syncthreads();
    if (t == 0) {
        float s = 0.f;
        for (int i = 0; i < 8; ++i) s += wred[i];
        s_rs = s;
    }
    __syncthreads();
    float inv_rs = 1.0f / (s_rs + 1e-8f);

    float u = 0.f;
#pragma unroll
    for (int ncp = 0; ncp < 16; ++ncp)
        u += g_upd_part[((b * 16 + ncp) * 8 + ks) * 256 + t];
    u *= inv_rs;
    s_x[t] = u;
    float hprev = g_slots[(b * KSL + ks) * 256 + t];
    s_h[t] = hprev;
    __syncthreads();

    float gx0 = b_ih[t], gx1 = b_ih[t + 256], gx2 = b_ih[t + 512];
    float gh0 = b_hh[t], gh1 = b_hh[t + 256], gh2 = b_hh[t + 512];
#pragma unroll 4
    for (int m = 0; m < 256; ++m) {
        float xm = s_x[m], hm = s_h[m];
        const float* wi = &W_ih[m * 768];
        const float* wh = &W_hh[m * 768];
        gx0 += xm * wi[t]; gx1 += xm * wi[t + 256]; gx2 += xm * wi[t + 512];
        gh0 += hm * wh[t]; gh1 += hm * wh[t + 256]; gh2 += hm * wh[t + 512];
    }
    float r = sigmoidf_(gx0 + gh0);
    float z = sigmoidf_(gx1 + gh1);
    float n = tanhf(gx2 + r * gh2);
    float h = (1.0f - z) * n + z * hprev;

    float s1 = h, s2 = h * h;
#pragma unroll
    for (int o = 16; o > 0; o >>= 1) {
        s1 += __shfl_xor_sync(0xffffffffu, s1, o);
        s2 += __shfl_xor_sync(0xffffffffu, s2, o);
    }
    __syncthreads();
    if (lane == 0) { wred[w] = s1; wred2[w] = s2; }
    __syncthreads();
    float S = 0.f, S2 = 0.f;
#pragma unroll
    for (int i = 0; i < 8; ++i) { S += wred[i]; S2 += wred2[i]; }
    float mean = S * (1.0f / 256.0f);
    float var  = S2 * (1.0f / 256.0f) - mean * mean;
    float sn = (h - mean) * rsqrtf(var + 1e-5f) * lng[t] + lnb[t];
    s_x[t] = sn;
    __syncthreads();

    float m0 = bm1[t], m1 = bm1[t + 256];
#pragma unroll 4
    for (int j = 0; j < 256; ++j) {
        float s = s_x[j];
        m0 += s * Wm1[j * 512 + t];
        m1 += s * Wm1[j * 512 + t + 256];
    }
    s_t2[t]       = gelu_exact(m0);
    s_t2[t + 256] = gelu_exact(m1);
    __syncthreads();
    float out = bm2[t];
#pragma unroll 4
    for (int j = 0; j < 512; ++j) out += s_t2[j] * Wm2[j * 256 + t];
    g_slots[(b * KSL + ks) * 256 + t] = h + out;
}

// ------------------------- 9) pack outputs ---------------------------------
__global__ void writeout_kernel(float* __restrict__ out) {
    int i = blockIdx.x * 256 + threadIdx.x;   // < 1179648
    const int SZ_SLOTS = Bsz * KSL * DS;      // 65536
    const int SZ_ATTN  = Bsz * KSL * Nn;      // 1048576
    const int SZ_HALF  = Bsz * KSL * DH;      // 32768
    if (i < SZ_SLOTS) {
        out[i] = g_slots[i];
    } else if (i < SZ_SLOTS + SZ_ATTN) {
        out[i] = g_attn[i - SZ_SLOTS];
    } else if (i < SZ_SLOTS + SZ_ATTN + SZ_HALF) {
        int j = i - SZ_SLOTS - SZ_ATTN;
        int bk = j >> 7, d = j & 127;
        out[i] = g_slots[bk * 256 + d];
    } else if (i < SZ_SLOTS + SZ_ATTN + 2 * SZ_HALF) {
        int j = i - SZ_SLOTS - SZ_ATTN - SZ_HALF;
        int bk = j >> 7, d = j & 127;
        out[i] = g_slots[bk * 256 + 128 + d];
    }
}

// ------------------------- launch ------------------------------------------
extern "C" void kernel_launch(void* const* d_in, const int* in_sizes, int n_in,
                              void* d_out, int out_size) {
    const float* features = (const float*)d_in[0];
    const float* Wi1  = (const float*)d_in[1];
    const float* bi1  = (const float*)d_in[2];
    const float* Wi2  = (const float*)d_in[3];
    const float* bi2  = (const float*)d_in[4];
    const float* Wp   = (const float*)d_in[5];
    const float* bp   = (const float*)d_in[6];
    const float* ln_in_g = (const float*)d_in[7];
    const float* ln_in_b = (const float*)d_in[8];
    const float* Wqs  = (const float*)d_in[9];
    const float* Wks  = (const float*)d_in[10];
    const float* Wqt  = (const float*)d_in[11];
    const float* Wkt  = (const float*)d_in[12];
    const float* W_ih = (const float*)d_in[13];
    const float* W_hh = (const float*)d_in[14];
    const float* b_ih = (const float*)d_in[15];
    const float* b_hh = (const float*)d_in[16];
    const float* ln_g = (const float*)d_in[17];
    const float* ln_b = (const float*)d_in[18];
    const float* Wm1  = (const float*)d_in[19];
    const float* bm1  = (const float*)d_in[20];
    const float* Wm2  = (const float*)d_in[21];
    const float* bm2  = (const float*)d_in[22];
    float* out = (float*)d_out;

    pool_part_kernel<<<dim3(3, 8, 32), 256>>>(features);
    pool_reduce_kernel<<<dim3(3, 32), 256>>>();
    slots_init1_kernel<<<dim3(2, 32), 256>>>(Wi1, bi1);
    slots_init2_kernel<<<dim3(8, 32), 256>>>(Wi2, bi2);
    gemm_ln_tc<<<2048, 256>>>(features, Wp, bp, ln_in_g, ln_in_b);
    kproj_tc<<<dim3(2048, 2), 256>>>(Wks, Wkt);

    for (int it = 0; it < NITER; ++it) {
        qproj_kernel<<<dim3(32, 8), 256>>>(Wqs, Wqt);
        logits_softmax_kernel<<<dim3(128, 32), 256>>>();
        upd1_kernel<<<dim3(16, 32), 256>>>();
        gru_mlp_kernel<<<dim3(8, 32), 256>>>(W_ih, W_hh, b_ih, b_hh,
                                             ln_g, ln_b, Wm1, bm1, Wm2, bm2);
    }
    writeout_kernel<<<4608, 256>>>(out);
}

// round 3
// speedup vs baseline: 1.9741x; 1.3203x over previous
#include <cuda_runtime.h>
#include <math.h>
#include <stdint.h>

#define Bsz   32
#define Nn    4096
#define DIN   768
#define DS    256
#define KSL   8
#define DH    128
#define NITER 3
#define MROWS (Bsz*Nn)   // 131072

// ------------------------- scratch (device globals, no allocs) -------------
__device__ float g_pool_part[Bsz*8*DIN];
__device__ float g_pool[Bsz*DIN];
__device__ float g_t1[Bsz*512];
__device__ float g_slots[Bsz*KSL*DS];
__device__ float g_inputs[MROWS*DS];      // 134 MB
__device__ float g_kcat[MROWS*DS];        // 134 MB
__device__ float g_qcat[Bsz*KSL*DS];
__device__ float g_attn[Bsz*KSL*Nn];
__device__ float g_rowsum_part[Bsz*KSL*128];
__device__ float g_upd_part[Bsz*16*KSL*DS];

__device__ __forceinline__ float gelu_exact(float x) {
    return 0.5f * x * (1.0f + erff(x * 0.70710678118654752f));
}
__device__ __forceinline__ float sigmoidf_(float x) {
    return 1.0f / (1.0f + expf(-x));
}
__device__ __forceinline__ void mma_tf32(float* c, const uint32_t* a,
                                         uint32_t b0, uint32_t b1) {
    asm volatile(
        "mma.sync.aligned.m16n8k8.row.col.f32.tf32.tf32.f32 "
        "{%0,%1,%2,%3}, {%4,%5,%6,%7}, {%8,%9}, {%0,%1,%2,%3};\n"
        : "+f"(c[0]), "+f"(c[1]), "+f"(c[2]), "+f"(c[3])
        : "r"(a[0]), "r"(a[1]), "r"(a[2]), "r"(a[3]), "r"(b0), "r"(b1));
}
__device__ __forceinline__ void cp16(uint32_t* smem_dst, const float* gsrc) {
    unsigned sa = (unsigned)__cvta_generic_to_shared(smem_dst);
    asm volatile("cp.async.cg.shared.global [%0], [%1], 16;\n"
                 :: "r"(sa), "l"(gsrc));
}
__device__ __forceinline__ void cp_commit() {
    asm volatile("cp.async.commit_group;\n");
}
template <int N>
__device__ __forceinline__ void cp_wait() {
    asm volatile("cp.async.wait_group %0;\n" :: "n"(N));
}

// ------------------------- 1) feature pooling ------------------------------
__global__ void pool_part_kernel(const float* __restrict__ feat) {
    int d  = blockIdx.x * 256 + threadIdx.x;   // < 768
    int nc = blockIdx.y;
    int b  = blockIdx.z;
    float s = 0.f;
    const float* p = feat + (size_t)(b * Nn + nc * 512) * DIN + d;
    for (int n = 0; n < 512; ++n) s += p[(size_t)n * DIN];
    g_pool_part[(b * 8 + nc) * DIN + d] = s;
}
__global__ void pool_reduce_kernel() {
    int d = blockIdx.x * 256 + threadIdx.x;
    int b = blockIdx.y;
    float s = 0.f;
    for (int i = 0; i < 8; ++i) s += g_pool_part[(b * 8 + i) * DIN + d];
    g_pool[b * DIN + d] = s * (1.0f / (float)Nn);
}

// ------------------------- 2) slot init MLP --------------------------------
__global__ void slots_init1_kernel(const float* __restrict__ Wi1,
                                   const float* __restrict__ bi1) {
    __shared__ float s_pool[DIN];
    int t = threadIdx.x;
    int b = blockIdx.y;
    int j = blockIdx.x * 256 + t;              // < 512
    for (int i = t; i < DIN; i += 256) s_pool[i] = g_pool[b * DIN + i];
    __syncthreads();
    float acc = bi1[j];
    for (int k = 0; k < DIN; ++k) acc += s_pool[k] * Wi1[k * 512 + j];
    g_t1[b * 512 + j] = gelu_exact(acc);
}
__global__ void slots_init2_kernel(const float* __restrict__ Wi2,
                                   const float* __restrict__ bi2) {
    __shared__ float s_t[512];
    int t = threadIdx.x;
    int b = blockIdx.y;
    int j = blockIdx.x * 256 + t;              // < 2048
    s_t[t] = g_t1[b * 512 + t];
    s_t[t + 256] = g_t1[b * 512 + t + 256];
    __syncthreads();
    float acc = bi2[j];
    for (int k = 0; k < 512; ++k) acc += s_t[k] * Wi2[k * 2048 + j];
    g_slots[b * 2048 + j] = acc;
}

// ------------------------- 3) tf32 TC GEMM + fused LN (pipelined) ----------
// inputs = LN(feat @ Wp + bp). BM=128, BN=256, BK=32, 512 threads (16 warps,
// 4x4), warp tile 32x64, 2-stage cp.async double buffer, dynamic smem.
#define GL_AS_STRIDE 36
#define GL_BS_STRIDE 264
#define GL_AS_SZ (128*GL_AS_STRIDE)     // 4608
#define GL_BS_SZ (32*GL_BS_STRIDE)      // 8448
#define GL_SMEM_BYTES ((2*GL_AS_SZ + 2*GL_BS_SZ)*4)   // 104448

extern __shared__ uint32_t g_dyn[];

__device__ __forceinline__ void gl_load_stage(
    uint32_t* As, uint32_t* Bs, const float* __restrict__ feat,
    const float* __restrict__ Wp, int bRow, int k0, int t) {
#pragma unroll
    for (int i = 0; i < 2; ++i) {
        int idx = t + 512 * i;                 // 0..1023
        int row = idx >> 3, q = idx & 7;
        cp16(&As[row * GL_AS_STRIDE + q * 4],
             &feat[(size_t)(bRow + row) * DIN + k0 + q * 4]);
    }
#pragma unroll
    for (int i = 0; i < 4; ++i) {
        int idx = t + 512 * i;                 // 0..2047
        int kk = idx >> 6, cq = idx & 63;
        cp16(&Bs[kk * GL_BS_STRIDE + cq * 4],
             &Wp[(size_t)(k0 + kk) * 256 + cq * 4]);
    }
}

__global__ void __launch_bounds__(512)
gemm_ln_tc(const float* __restrict__ feat, const float* __restrict__ Wp,
           const float* __restrict__ bp, const float* __restrict__ lng,
           const float* __restrict__ lnb) {
    uint32_t* AsBuf = g_dyn;                       // 2 stages A
    uint32_t* BsBuf = g_dyn + 2 * GL_AS_SZ;        // 2 stages B
    __shared__ float s_sum[128][4];
    __shared__ float s_sq[128][4];

    int t = threadIdx.x;
    int lane = t & 31, wid = t >> 5;
    int wr = wid >> 2, wc = wid & 3;    // 4x4 warps: 32 rows, 64 cols each
    int g = lane >> 2, tg = lane & 3;
    int bRow = blockIdx.x * 128;

    float c[2][8][4];
#pragma unroll
    for (int mt = 0; mt < 2; ++mt)
#pragma unroll
        for (int nt = 0; nt < 8; ++nt)
#pragma unroll
            for (int j = 0; j < 4; ++j) c[mt][nt][j] = 0.f;

    gl_load_stage(AsBuf, BsBuf, feat, Wp, bRow, 0, t);
    cp_commit();

    const int NK = DIN / 32;    // 24
    for (int kt = 0; kt < NK; ++kt) {
        int s = kt & 1;
        if (kt + 1 < NK) {
            gl_load_stage(AsBuf + ((kt + 1) & 1) * GL_AS_SZ,
                          BsBuf + ((kt + 1) & 1) * GL_BS_SZ,
                          feat, Wp, bRow, (kt + 1) * 32, t);
            cp_commit();
            cp_wait<1>();
        } else {
            cp_wait<0>();
        }
        __syncthreads();
        uint32_t* As = AsBuf + s * GL_AS_SZ;
        uint32_t* Bs = BsBuf + s * GL_BS_SZ;
#pragma unroll
        for (int ks = 0; ks < 4; ++ks) {
            uint32_t a[2][4];
#pragma unroll
            for (int mt = 0; mt < 2; ++mt) {
                int r = wr * 32 + mt * 16 + g;
                a[mt][0] = As[r * GL_AS_STRIDE + ks * 8 + tg];
                a[mt][1] = As[(r + 8) * GL_AS_STRIDE + ks * 8 + tg];
                a[mt][2] = As[r * GL_AS_STRIDE + ks * 8 + tg + 4];
                a[mt][3] = As[(r + 8) * GL_AS_STRIDE + ks * 8 + tg + 4];
            }
#pragma unroll
            for (int nt = 0; nt < 8; ++nt) {
                int cb = wc * 64 + nt * 8 + g;
                uint32_t b0 = Bs[(ks * 8 + tg) * GL_BS_STRIDE + cb];
                uint32_t b1 = Bs[(ks * 8 + tg + 4) * GL_BS_STRIDE + cb];
                mma_tf32(c[0][nt], a[0], b0, b1);
                mma_tf32(c[1][nt], a[1], b0, b1);
            }
        }
        __syncthreads();
    }

    // --- epilogue: bias + LN over 256 cols, from register fragments ---
    float2 bpv[8], gv[8], bvv[8];
#pragma unroll
    for (int nt = 0; nt < 8; ++nt) {
        int cb = wc * 64 + nt * 8 + tg * 2;
        bpv[nt] = *reinterpret_cast<const float2*>(&bp[cb]);
        gv[nt]  = *reinterpret_cast<const float2*>(&lng[cb]);
        bvv[nt] = *reinterpret_cast<const float2*>(&lnb[cb]);
    }
    float ls[2][2], lq[2][2];
#pragma unroll
    for (int mt = 0; mt < 2; ++mt)
#pragma unroll
        for (int h = 0; h < 2; ++h) { ls[mt][h] = 0.f; lq[mt][h] = 0.f; }
#pragma unroll
    for (int mt = 0; mt < 2; ++mt)
#pragma unroll
        for (int nt = 0; nt < 8; ++nt) {
            c[mt][nt][0] += bpv[nt].x;
            c[mt][nt][1] += bpv[nt].y;
            c[mt][nt][2] += bpv[nt].x;
            c[mt][nt][3] += bpv[nt].y;
            ls[mt][0] += c[mt][nt][0] + c[mt][nt][1];
            lq[mt][0] += c[mt][nt][0] * c[mt][nt][0] + c[mt][nt][1] * c[mt][nt][1];
            ls[mt][1] += c[mt][nt][2] + c[mt][nt][3];
            lq[mt][1] += c[mt][nt][2] * c[mt][nt][2] + c[mt][nt][3] * c[mt][nt][3];
        }
#pragma unroll
    for (int mt = 0; mt < 2; ++mt)
#pragma unroll
        for (int h = 0; h < 2; ++h) {
            ls[mt][h] += __shfl_xor_sync(0xffffffffu, ls[mt][h], 1);
            ls[mt][h] += __shfl_xor_sync(0xffffffffu, ls[mt][h], 2);
            lq[mt][h] += __shfl_xor_sync(0xffffffffu, lq[mt][h], 1);
            lq[mt][h] += __shfl_xor_sync(0xffffffffu, lq[mt][h], 2);
        }
    if (tg == 0) {
#pragma unroll
        for (int mt = 0; mt < 2; ++mt)
#pragma unroll
            for (int h = 0; h < 2; ++h) {
                int rl = wr * 32 + mt * 16 + h * 8 + g;
                s_sum[rl][wc] = ls[mt][h];
                s_sq[rl][wc]  = lq[mt][h];
            }
    }
    __syncthreads();
    float mean[2][2], inv[2][2];
#pragma unroll
    for (int mt = 0; mt < 2; ++mt)
#pragma unroll
        for (int h = 0; h < 2; ++h) {
            int rl = wr * 32 + mt * 16 + h * 8 + g;
            float S = s_sum[rl][0] + s_sum[rl][1] + s_sum[rl][2] + s_sum[rl][3];
            float Q = s_sq[rl][0] + s_sq[rl][1] + s_sq[rl][2] + s_sq[rl][3];
            float m = S * (1.0f / 256.0f);
            float v = Q * (1.0f / 256.0f) - m * m;
            mean[mt][h] = m;
            inv[mt][h]  = rsqrtf(v + 1e-5f);
        }
#pragma unroll
    for (int mt = 0; mt < 2; ++mt)
#pragma unroll
        for (int nt = 0; nt < 8; ++nt)
#pragma unroll
            for (int h = 0; h < 2; ++h) {
                int rl = wr * 32 + mt * 16 + h * 8 + g;
                size_t row = (size_t)(bRow + rl);
                int cb = wc * 64 + nt * 8 + tg * 2;
                float2 o;
                o.x = (c[mt][nt][h * 2]     - mean[mt][h]) * inv[mt][h] * gv[nt].x + bvv[nt].x;
                o.y = (c[mt][nt][h * 2 + 1] - mean[mt][h]) * inv[mt][h] * gv[nt].y + bvv[nt].y;
                *reinterpret_cast<float2*>(&g_inputs[row * 256 + cb]) = o;
            }
}

// ------------------------- 4) tf32 TC k-projection -------------------------
__global__ void __launch_bounds__(256)
kproj_tc(const float* __restrict__ Wks, const float* __restrict__ Wkt) {
    __shared__ uint32_t As[64][36];
    __shared__ uint32_t Bs2[32][136];

    int t = threadIdx.x;
    int lane = t & 31, wid = t >> 5;
    int wr = wid >> 2, wc = wid & 3;
    int g = lane >> 2, tg = lane & 3;
    int bRow = blockIdx.x * 64;
    int z = blockIdx.y;
    const float* W = z ? Wkt : Wks;

    float c[2][4][4];
#pragma unroll
    for (int mt = 0; mt < 2; ++mt)
#pragma unroll
        for (int nt = 0; nt < 4; ++nt)
#pragma unroll
            for (int j = 0; j < 4; ++j) c[mt][nt][j] = 0.f;

    for (int k0 = 0; k0 < 128; k0 += 32) {
#pragma unroll
        for (int i = 0; i < 2; ++i) {
            int idx = t + 256 * i;
            int row = idx >> 3, q = idx & 7;
            float4 v = *reinterpret_cast<const float4*>(
                &g_inputs[(size_t)(bRow + row) * 256 + z * 128 + k0 + q * 4]);
            As[row][q * 4 + 0] = __float_as_uint(v.x);
            As[row][q * 4 + 1] = __float_as_uint(v.y);
            As[row][q * 4 + 2] = __float_as_uint(v.z);
            As[row][q * 4 + 3] = __float_as_uint(v.w);
        }
#pragma unroll
        for (int i = 0; i < 4; ++i) {
            int idx = t + 256 * i;             // 0..1023
            int kk = idx >> 5, cq = idx & 31;
            float4 v = *reinterpret_cast<const float4*>(
                &W[(size_t)(k0 + kk) * 128 + cq * 4]);
            Bs2[kk][cq * 4 + 0] = __float_as_uint(v.x);
            Bs2[kk][cq * 4 + 1] = __float_as_uint(v.y);
            Bs2[kk][cq * 4 + 2] = __float_as_uint(v.z);
            Bs2[kk][cq * 4 + 3] = __float_as_uint(v.w);
        }
        __syncthreads();
#pragma unroll
        for (int ks = 0; ks < 4; ++ks) {
            uint32_t a[2][4];
#pragma unroll
            for (int mt = 0; mt < 2; ++mt) {
                int r = wr * 32 + mt * 16 + g;
                a[mt][0] = As[r][ks * 8 + tg];
                a[mt][1] = As[r + 8][ks * 8 + tg];
                a[mt][2] = As[r][ks * 8 + tg + 4];
                a[mt][3] = As[r + 8][ks * 8 + tg + 4];
            }
#pragma unroll
            for (int nt = 0; nt < 4; ++nt) {
                int cb = wc * 32 + nt * 8 + g;
                uint32_t b0 = Bs2[ks * 8 + tg][cb];
                uint32_t b1 = Bs2[ks * 8 + tg + 4][cb];
                mma_tf32(c[0][nt], a[0], b0, b1);
                mma_tf32(c[1][nt], a[1], b0, b1);
            }
        }
        __syncthreads();
    }
#pragma unroll
    for (int mt = 0; mt < 2; ++mt)
#pragma unroll
        for (int nt = 0; nt < 4; ++nt)
#pragma unroll
            for (int h = 0; h < 2; ++h) {
                int rl = wr * 32 + mt * 16 + h * 8 + g;
                size_t row = (size_t)(bRow + rl);
                int cb = wc * 32 + nt * 8 + tg * 2;
                float2 o;
                o.x = c[mt][nt][h * 2];
                o.y = c[mt][nt][h * 2 + 1];
                *reinterpret_cast<float2*>(&g_kcat[row * 256 + z * 128 + cb]) = o;
            }
}

// ------------------------- 5) q projection (scales prefolded) --------------
__global__ void qproj_kernel(const float* __restrict__ Wqs,
                             const float* __restrict__ Wqt) {
    __shared__ float s_slot[256];
    int t = threadIdx.x;
    int b = blockIdx.x, ks = blockIdx.y;
    s_slot[t] = g_slots[(b * KSL + ks) * 256 + t];
    __syncthreads();
    int half = t >> 7;
    int cc   = t & 127;
    const float* W = half ? Wqt : Wqs;
    const float rs = 0.08838834764831845f;    // 128^-0.5
    float sc = half ? 0.3f * rs : 0.7f * rs;
    float acc = 0.f;
    const float* sp = &s_slot[half * 128];
#pragma unroll 8
    for (int j = 0; j < 128; ++j) acc += sp[j] * W[j * 128 + cc];
    g_qcat[(b * KSL + ks) * 256 + t] = acc * sc;
}

// ------------------------- 6) logits + softmax(K) + rowsum partials --------
__global__ void __launch_bounds__(256)
logits_softmax_kernel() {
    __shared__ float s_q[8 * 256];
    __shared__ float s_k[32 * 260];
    __shared__ float s_m[32], s_e[32];
    __shared__ float s_a[8][32];
    int t  = threadIdx.x;
    int nc = blockIdx.x, b = blockIdx.y;

#pragma unroll
    for (int i = 0; i < 8; ++i) s_q[t + 256 * i] = g_qcat[b * 2048 + t + 256 * i];
#pragma unroll
    for (int i = 0; i < 8; ++i) {
        int idx = t + 256 * i;                  // float4 units, 0..2047
        int n = idx >> 6, dq = idx & 63;
        float4 v = *reinterpret_cast<const float4*>(
            &g_kcat[(size_t)(b * Nn + nc * 32 + n) * 256 + dq * 4]);
        *reinterpret_cast<float4*>(&s_k[n * 260 + dq * 4]) = v;
    }
    __syncthreads();

    int kk = t >> 5, nl = t & 31;
    const float4* q4 = reinterpret_cast<const float4*>(&s_q[kk * 256]);
    const float4* k4 = reinterpret_cast<const float4*>(&s_k[nl * 260]);
    float acc = 0.f;
#pragma unroll 8
    for (int d = 0; d < 64; ++d) {
        float4 qv = q4[d], kv = k4[d];
        acc += qv.x * kv.x + qv.y * kv.y + qv.z * kv.z + qv.w * kv.w;
    }
    s_a[kk][nl] = acc;
    __syncthreads();

    if (kk == 0) {
        float m = -1e30f;
#pragma unroll
        for (int i = 0; i < 8; ++i) m = fmaxf(m, s_a[i][nl]);
        float e = 0.f;
#pragma unroll
        for (int i = 0; i < 8; ++i) e += expf(s_a[i][nl] - m);
        s_m[nl] = m; s_e[nl] = e;
    }
    __syncthreads();

    float a = expf(acc - s_m[nl]) / s_e[nl];
    g_attn[(size_t)(b * KSL + kk) * Nn + nc * 32 + nl] = a;
    s_a[kk][nl] = a;
    __syncthreads();

    if (nl == 0) {
        float s = 0.f;
#pragma unroll
        for (int i = 0; i < 32; ++i) s += s_a[kk][i];
        g_rowsum_part[(b * KSL + kk) * 128 + nc] = s;
    }
}

// ------------------------- 7) updates stage 1 (partials over n) ------------
__global__ void __launch_bounds__(256)
upd1_kernel() {
    __shared__ float s_a[8][256];
    int t  = threadIdx.x;
    int nc = blockIdx.x, b = blockIdx.y;
#pragma unroll
    for (int i = 0; i < 8; ++i) {
        int idx = t + 256 * i;
        int kk = idx >> 8, nl = idx & 255;
        s_a[kk][nl] = g_attn[(size_t)(b * KSL + kk) * Nn + nc * 256 + nl];
    }
    __syncthreads();
    float acc[8] = {0, 0, 0, 0, 0, 0, 0, 0};
    const float* ip = &g_inputs[(size_t)(b * Nn + nc * 256) * 256 + t];
#pragma unroll 4
    for (int nl = 0; nl < 256; ++nl) {
        float inp = ip[(size_t)nl * 256];
#pragma unroll
        for (int kk = 0; kk < 8; ++kk) acc[kk] += s_a[kk][nl] * inp;
    }
#pragma unroll
    for (int kk = 0; kk < 8; ++kk)
        g_upd_part[((b * 16 + nc) * 8 + kk) * 256 + t] = acc[kk];
}

// ------------------------- 8) fused finalize + GRU + LN + MLP --------------
// 768 threads: one per gate column.
__global__ void __launch_bounds__(768)
gru_mlp_kernel(const float* __restrict__ W_ih, const float* __restrict__ W_hh,
               const float* __restrict__ b_ih, const float* __restrict__ b_hh,
               const float* __restrict__ lng, const float* __restrict__ lnb,
               const float* __restrict__ Wm1, const float* __restrict__ bm1,
               const float* __restrict__ Wm2, const float* __restrict__ bm2) {
    __shared__ float s_x[256], s_h[256], s_t2[512];
    __shared__ float s_gx[768], s_gh[768];
    __shared__ float wred[8], wred2[8];
    __shared__ float s_rs;
    int t  = threadIdx.x;
    int ks = blockIdx.x, b = blockIdx.y;
    int lane = t & 31, w = t >> 5;

    // rowsum reduce (128 partials) with warps 0..3
    float v = (t < 128) ? g_rowsum_part[(b * KSL + ks) * 128 + t] : 0.f;
#pragma unroll
    for (int o = 16; o > 0; o >>= 1) v += __shfl_xor_sync(0xffffffffu, v, o);
    if (lane == 0 && w < 4) wred[w] = v;
    __syncthreads();
    if (t == 0) s_rs = wred[0] + wred[1] + wred[2] + wred[3];
    __syncthreads();
    float inv_rs = 1.0f / (s_rs + 1e-8f);

    if (t < 256) {
        float u = 0.f;
#pragma unroll
        for (int ncp = 0; ncp < 16; ++ncp)
            u += g_upd_part[((b * 16 + ncp) * 8 + ks) * 256 + t];
        s_x[t] = u * inv_rs;
        s_h[t] = g_slots[(b * KSL + ks) * 256 + t];
    }
    __syncthreads();

    // gates: thread t computes gate column t (of 768)
    {
        float gx = b_ih[t], gh = b_hh[t];
#pragma unroll 4
        for (int m = 0; m < 256; ++m) {
            gx += s_x[m] * W_ih[m * 768 + t];
            gh += s_h[m] * W_hh[m * 768 + t];
        }
        s_gx[t] = gx;
        s_gh[t] = gh;
    }
    __syncthreads();

    float h = 0.f, hprev = 0.f;
    if (t < 256) {
        hprev = s_h[t];
        float r = sigmoidf_(s_gx[t] + s_gh[t]);
        float z = sigmoidf_(s_gx[t + 256] + s_gh[t + 256]);
        float n = tanhf(s_gx[t + 512] + r * s_gh[t + 512]);
        h = (1.0f - z) * n + z * hprev;
    }

    // LN over 256 (warps 0..7 hold the data)
    float s1 = h, s2 = h * h;
#pragma unroll
    for (int o = 16; o > 0; o >>= 1) {
        s1 += __shfl_xor_sync(0xffffffffu, s1, o);
        s2 += __shfl_xor_sync(0xffffffffu, s2, o);
    }
    if (lane == 0 && w < 8) { wred[w] = s1; wred2[w] = s2; }
    __syncthreads();
    if (t < 256) {
        float S = 0.f, S2 = 0.f;
#pragma unroll
        for (int i = 0; i < 8; ++i) { S += wred[i]; S2 += wred2[i]; }
        float mean = S * (1.0f / 256.0f);
        float var  = S2 * (1.0f / 256.0f) - mean * mean;
        float sn = (h - mean) * rsqrtf(var + 1e-5f) * lng[t] + lnb[t];
        s_x[t] = sn;
    }
    __syncthreads();

    // MLP layer 1: threads 0..511, one column each
    if (t < 512) {
        float m0 = bm1[t];
#pragma unroll 4
        for (int j = 0; j < 256; ++j) m0 += s_x[j] * Wm1[j * 512 + t];
        s_t2[t] = gelu_exact(m0);
    }
    __syncthreads();

    // MLP layer 2: threads 0..255
    if (t < 256) {
        float out = bm2[t];
#pragma unroll 4
        for (int j = 0; j < 512; ++j) out += s_t2[j] * Wm2[j * 256 + t];
        g_slots[(b * KSL + ks) * 256 + t] = h + out;
    }
}

// ------------------------- 9) pack outputs ---------------------------------
__global__ void writeout_kernel(float* __restrict__ out) {
    int i = blockIdx.x * 256 + threadIdx.x;   // < 1179648
    const int SZ_SLOTS = Bsz * KSL * DS;      // 65536
    const int SZ_ATTN  = Bsz * KSL * Nn;      // 1048576
    const int SZ_HALF  = Bsz * KSL * DH;      // 32768
    if (i < SZ_SLOTS) {
        out[i] = g_slots[i];
    } else if (i < SZ_SLOTS + SZ_ATTN) {
        out[i] = g_attn[i - SZ_SLOTS];
    } else if (i < SZ_SLOTS + SZ_ATTN + SZ_HALF) {
        int j = i - SZ_SLOTS - SZ_ATTN;
        int bk = j >> 7, d = j & 127;
        out[i] = g_slots[bk * 256 + d];
    } else if (i < SZ_SLOTS + SZ_ATTN + 2 * SZ_HALF) {
        int j = i - SZ_SLOTS - SZ_ATTN - SZ_HALF;
        int bk = j >> 7, d = j & 127;
        out[i] = g_slots[bk * 256 + 128 + d];
    }
}

// ------------------------- launch ------------------------------------------
extern "C" void kernel_launch(void* const* d_in, const int* in_sizes, int n_in,
                              void* d_out, int out_size) {
    const float* features = (const float*)d_in[0];
    const float* Wi1  = (const float*)d_in[1];
    const float* bi1  = (const float*)d_in[2];
    const float* Wi2  = (const float*)d_in[3];
    const float* bi2  = (const float*)d_in[4];
    const float* Wp   = (const float*)d_in[5];
    const float* bp   = (const float*)d_in[6];
    const float* ln_in_g = (const float*)d_in[7];
    const float* ln_in_b = (const float*)d_in[8];
    const float* Wqs  = (const float*)d_in[9];
    const float* Wks  = (const float*)d_in[10];
    const float* Wqt  = (const float*)d_in[11];
    const float* Wkt  = (const float*)d_in[12];
    const float* W_ih = (const float*)d_in[13];
    const float* W_hh = (const float*)d_in[14];
    const float* b_ih = (const float*)d_in[15];
    const float* b_hh = (const float*)d_in[16];
    const float* ln_g = (const float*)d_in[17];
    const float* ln_b = (const float*)d_in[18];
    const float* Wm1  = (const float*)d_in[19];
    const float* bm1  = (const float*)d_in[20];
    const float* Wm2  = (const float*)d_in[21];
    const float* bm2  = (const float*)d_in[22];
    float* out = (float*)d_out;

    cudaFuncSetAttribute(gemm_ln_tc, cudaFuncAttributeMaxDynamicSharedMemorySize,
                         GL_SMEM_BYTES);

    pool_part_kernel<<<dim3(3, 8, 32), 256>>>(features);
    pool_reduce_kernel<<<dim3(3, 32), 256>>>();
    slots_init1_kernel<<<dim3(2, 32), 256>>>(Wi1, bi1);
    slots_init2_kernel<<<dim3(8, 32), 256>>>(Wi2, bi2);
    gemm_ln_tc<<<1024, 512, GL_SMEM_BYTES>>>(features, Wp, bp, ln_in_g, ln_in_b);
    kproj_tc<<<dim3(2048, 2), 256>>>(Wks, Wkt);

    for (int it = 0; it < NITER; ++it) {
        qproj_kernel<<<dim3(32, 8), 256>>>(Wqs, Wqt);
        logits_softmax_kernel<<<dim3(128, 32), 256>>>();
        upd1_kernel<<<dim3(16, 32), 256>>>();
        gru_mlp_kernel<<<dim3(8, 32), 768>>>(W_ih, W_hh, b_ih, b_hh,
                                             ln_g, ln_b, Wm1, bm1, Wm2, bm2);
    }
    writeout_kernel<<<4608, 256>>>(out);
}

// round 4
// speedup vs baseline: 1.9749x; 1.0004x over previous
#include <cuda_runtime.h>
#include <math.h>
#include <stdint.h>

#define Bsz   32
#define Nn    4096
#define DIN   768
#define DS    256
#define KSL   8
#define DH    128
#define NITER 3
#define MROWS (Bsz*Nn)   // 131072

// ------------------------- scratch (device globals, no allocs) -------------
__device__ float g_pool_part[Bsz*8*DIN];
__device__ float g_pool[Bsz*DIN];
__device__ float g_t1[Bsz*512];
__device__ float g_slots[Bsz*KSL*DS];
__device__ float g_inputs[MROWS*DS];      // 134 MB
__device__ float g_kcat[MROWS*DS];        // 134 MB
__device__ float g_qcat[Bsz*KSL*DS];
__device__ float g_attn[Bsz*KSL*Nn];
__device__ float g_rowsum_part[Bsz*KSL*128];
__device__ float g_upd_part[Bsz*16*KSL*DS];

__device__ __forceinline__ float gelu_exact(float x) {
    return 0.5f * x * (1.0f + erff(x * 0.70710678118654752f));
}
__device__ __forceinline__ float sigmoidf_(float x) {
    return 1.0f / (1.0f + expf(-x));
}
__device__ __forceinline__ void mma_tf32(float* c, const uint32_t* a,
                                         uint32_t b0, uint32_t b1) {
    asm volatile(
        "mma.sync.aligned.m16n8k8.row.col.f32.tf32.tf32.f32 "
        "{%0,%1,%2,%3}, {%4,%5,%6,%7}, {%8,%9}, {%0,%1,%2,%3};\n"
        : "+f"(c[0]), "+f"(c[1]), "+f"(c[2]), "+f"(c[3])
        : "r"(a[0]), "r"(a[1]), "r"(a[2]), "r"(a[3]), "r"(b0), "r"(b1));
}
__device__ __forceinline__ void cp16(uint32_t* smem_dst, const float* gsrc) {
    unsigned sa = (unsigned)__cvta_generic_to_shared(smem_dst);
    asm volatile("cp.async.cg.shared.global [%0], [%1], 16;\n"
                 :: "r"(sa), "l"(gsrc));
}
__device__ __forceinline__ void cp_commit() {
    asm volatile("cp.async.commit_group;\n");
}
template <int N>
__device__ __forceinline__ void cp_wait() {
    asm volatile("cp.async.wait_group %0;\n" :: "n"(N));
}

// ------------------------- 1) feature pooling ------------------------------
__global__ void pool_part_kernel(const float* __restrict__ feat) {
    int d  = blockIdx.x * 256 + threadIdx.x;   // < 768
    int nc = blockIdx.y;
    int b  = blockIdx.z;
    float s = 0.f;
    const float* p = feat + (size_t)(b * Nn + nc * 512) * DIN + d;
    for (int n = 0; n < 512; ++n) s += p[(size_t)n * DIN];
    g_pool_part[(b * 8 + nc) * DIN + d] = s;
}
__global__ void pool_reduce_kernel() {
    int d = blockIdx.x * 256 + threadIdx.x;
    int b = blockIdx.y;
    float s = 0.f;
    for (int i = 0; i < 8; ++i) s += g_pool_part[(b * 8 + i) * DIN + d];
    g_pool[b * DIN + d] = s * (1.0f / (float)Nn);
}

// ------------------------- 2) slot init MLP --------------------------------
__global__ void slots_init1_kernel(const float* __restrict__ Wi1,
                                   const float* __restrict__ bi1) {
    __shared__ float s_pool[DIN];
    int t = threadIdx.x;
    int b = blockIdx.y;
    int j = blockIdx.x * 256 + t;              // < 512
    for (int i = t; i < DIN; i += 256) s_pool[i] = g_pool[b * DIN + i];
    __syncthreads();
    float acc = bi1[j];
    for (int k = 0; k < DIN; ++k) acc += s_pool[k] * Wi1[k * 512 + j];
    g_t1[b * 512 + j] = gelu_exact(acc);
}
__global__ void slots_init2_kernel(const float* __restrict__ Wi2,
                                   const float* __restrict__ bi2) {
    __shared__ float s_t[512];
    int t = threadIdx.x;
    int b = blockIdx.y;
    int j = blockIdx.x * 256 + t;              // < 2048
    s_t[t] = g_t1[b * 512 + t];
    s_t[t + 256] = g_t1[b * 512 + t + 256];
    __syncthreads();
    float acc = bi2[j];
    for (int k = 0; k < 512; ++k) acc += s_t[k] * Wi2[k * 2048 + j];
    g_slots[b * 2048 + j] = acc;
}

// ------------------------- 3) tf32 TC GEMM + fused LN (pipelined) ----------
// inputs = LN(feat @ Wp + bp). BM=128, BN=256, BK=32, 512 threads (16 warps,
// 4x4), warp tile 32x64, 2-stage cp.async double buffer, dynamic smem.
#define GL_AS_STRIDE 36
#define GL_BS_STRIDE 264
#define GL_AS_SZ (128*GL_AS_STRIDE)     // 4608
#define GL_BS_SZ (32*GL_BS_STRIDE)      // 8448
#define GL_SMEM_BYTES ((2*GL_AS_SZ + 2*GL_BS_SZ)*4)   // 104448

extern __shared__ uint32_t g_dyn[];

__device__ __forceinline__ void gl_load_stage(
    uint32_t* As, uint32_t* Bs, const float* __restrict__ feat,
    const float* __restrict__ Wp, int bRow, int k0, int t) {
#pragma unroll
    for (int i = 0; i < 2; ++i) {
        int idx = t + 512 * i;                 // 0..1023
        int row = idx >> 3, q = idx & 7;
        cp16(&As[row * GL_AS_STRIDE + q * 4],
             &feat[(size_t)(bRow + row) * DIN + k0 + q * 4]);
    }
#pragma unroll
    for (int i = 0; i < 4; ++i) {
        int idx = t + 512 * i;                 // 0..2047
        int kk = idx >> 6, cq = idx & 63;
        cp16(&Bs[kk * GL_BS_STRIDE + cq * 4],
             &Wp[(size_t)(k0 + kk) * 256 + cq * 4]);
    }
}

__global__ void __launch_bounds__(512)
gemm_ln_tc(const float* __restrict__ feat, const float* __restrict__ Wp,
           const float* __restrict__ bp, const float* __restrict__ lng,
           const float* __restrict__ lnb) {
    uint32_t* AsBuf = g_dyn;                       // 2 stages A
    uint32_t* BsBuf = g_dyn + 2 * GL_AS_SZ;        // 2 stages B
    __shared__ float s_sum[128][4];
    __shared__ float s_sq[128][4];

    int t = threadIdx.x;
    int lane = t & 31, wid = t >> 5;
    int wr = wid >> 2, wc = wid & 3;    // 4x4 warps: 32 rows, 64 cols each
    int g = lane >> 2, tg = lane & 3;
    int bRow = blockIdx.x * 128;

    float c[2][8][4];
#pragma unroll
    for (int mt = 0; mt < 2; ++mt)
#pragma unroll
        for (int nt = 0; nt < 8; ++nt)
#pragma unroll
            for (int j = 0; j < 4; ++j) c[mt][nt][j] = 0.f;

    gl_load_stage(AsBuf, BsBuf, feat, Wp, bRow, 0, t);
    cp_commit();

    const int NK = DIN / 32;    // 24
    for (int kt = 0; kt < NK; ++kt) {
        int s = kt & 1;
        if (kt + 1 < NK) {
            gl_load_stage(AsBuf + ((kt + 1) & 1) * GL_AS_SZ,
                          BsBuf + ((kt + 1) & 1) * GL_BS_SZ,
                          feat, Wp, bRow, (kt + 1) * 32, t);
            cp_commit();
            cp_wait<1>();
        } else {
            cp_wait<0>();
        }
        __syncthreads();
        uint32_t* As = AsBuf + s * GL_AS_SZ;
        uint32_t* Bs = BsBuf + s * GL_BS_SZ;
#pragma unroll
        for (int ks = 0; ks < 4; ++ks) {
            uint32_t a[2][4];
#pragma unroll
            for (int mt = 0; mt < 2; ++mt) {
                int r = wr * 32 + mt * 16 + g;
                a[mt][0] = As[r * GL_AS_STRIDE + ks * 8 + tg];
                a[mt][1] = As[(r + 8) * GL_AS_STRIDE + ks * 8 + tg];
                a[mt][2] = As[r * GL_AS_STRIDE + ks * 8 + tg + 4];
                a[mt][3] = As[(r + 8) * GL_AS_STRIDE + ks * 8 + tg + 4];
            }
#pragma unroll
            for (int nt = 0; nt < 8; ++nt) {
                int cb = wc * 64 + nt * 8 + g;
                uint32_t b0 = Bs[(ks * 8 + tg) * GL_BS_STRIDE + cb];
                uint32_t b1 = Bs[(ks * 8 + tg + 4) * GL_BS_STRIDE + cb];
                mma_tf32(c[0][nt], a[0], b0, b1);
                mma_tf32(c[1][nt], a[1], b0, b1);
            }
        }
        __syncthreads();
    }

    // --- epilogue: bias + LN over 256 cols, from register fragments ---
    float2 bpv[8], gv[8], bvv[8];
#pragma unroll
    for (int nt = 0; nt < 8; ++nt) {
        int cb = wc * 64 + nt * 8 + tg * 2;
        bpv[nt] = *reinterpret_cast<const float2*>(&bp[cb]);
        gv[nt]  = *reinterpret_cast<const float2*>(&lng[cb]);
        bvv[nt] = *reinterpret_cast<const float2*>(&lnb[cb]);
    }
    float ls[2][2], lq[2][2];
#pragma unroll
    for (int mt = 0; mt < 2; ++mt)
#pragma unroll
        for (int h = 0; h < 2; ++h) { ls[mt][h] = 0.f; lq[mt][h] = 0.f; }
#pragma unroll
    for (int mt = 0; mt < 2; ++mt)
#pragma unroll
        for (int nt = 0; nt < 8; ++nt) {
            c[mt][nt][0] += bpv[nt].x;
            c[mt][nt][1] += bpv[nt].y;
            c[mt][nt][2] += bpv[nt].x;
            c[mt][nt][3] += bpv[nt].y;
            ls[mt][0] += c[mt][nt][0] + c[mt][nt][1];
            lq[mt][0] += c[mt][nt][0] * c[mt][nt][0] + c[mt][nt][1] * c[mt][nt][1];
            ls[mt][1] += c[mt][nt][2] + c[mt][nt][3];
            lq[mt][1] += c[mt][nt][2] * c[mt][nt][2] + c[mt][nt][3] * c[mt][nt][3];
        }
#pragma unroll
    for (int mt = 0; mt < 2; ++mt)
#pragma unroll
        for (int h = 0; h < 2; ++h) {
            ls[mt][h] += __shfl_xor_sync(0xffffffffu, ls[mt][h], 1);
            ls[mt][h] += __shfl_xor_sync(0xffffffffu, ls[mt][h], 2);
            lq[mt][h] += __shfl_xor_sync(0xffffffffu, lq[mt][h], 1);
            lq[mt][h] += __shfl_xor_sync(0xffffffffu, lq[mt][h], 2);
        }
    if (tg == 0) {
#pragma unroll
        for (int mt = 0; mt < 2; ++mt)
#pragma unroll
            for (int h = 0; h < 2; ++h) {
                int rl = wr * 32 + mt * 16 + h * 8 + g;
                s_sum[rl][wc] = ls[mt][h];
                s_sq[rl][wc]  = lq[mt][h];
            }
    }
    __syncthreads();
    float mean[2][2], inv[2][2];
#pragma unroll
    for (int mt = 0; mt < 2; ++mt)
#pragma unroll
        for (int h = 0; h < 2; ++h) {
            int rl = wr * 32 + mt * 16 + h * 8 + g;
            float S = s_sum[rl][0] + s_sum[rl][1] + s_sum[rl][2] + s_sum[rl][3];
            float Q = s_sq[rl][0] + s_sq[rl][1] + s_sq[rl][2] + s_sq[rl][3];
            float m = S * (1.0f / 256.0f);
            float v = Q * (1.0f / 256.0f) - m * m;
            mean[mt][h] = m;
            inv[mt][h]  = rsqrtf(v + 1e-5f);
        }
#pragma unroll
    for (int mt = 0; mt < 2; ++mt)
#pragma unroll
        for (int nt = 0; nt < 8; ++nt)
#pragma unroll
            for (int h = 0; h < 2; ++h) {
                int rl = wr * 32 + mt * 16 + h * 8 + g;
                size_t row = (size_t)(bRow + rl);
                int cb = wc * 64 + nt * 8 + tg * 2;
                float2 o;
                o.x = (c[mt][nt][h * 2]     - mean[mt][h]) * inv[mt][h] * gv[nt].x + bvv[nt].x;
                o.y = (c[mt][nt][h * 2 + 1] - mean[mt][h]) * inv[mt][h] * gv[nt].y + bvv[nt].y;
                *reinterpret_cast<float2*>(&g_inputs[row * 256 + cb]) = o;
            }
}

// ------------------------- 4) tf32 TC k-projection -------------------------
__global__ void __launch_bounds__(256)
kproj_tc(const float* __restrict__ Wks, const float* __restrict__ Wkt) {
    __shared__ uint32_t As[64][36];
    __shared__ uint32_t Bs2[32][136];

    int t = threadIdx.x;
    int lane = t & 31, wid = t >> 5;
    int wr = wid >> 2, wc = wid & 3;
    int g = lane >> 2, tg = lane & 3;
    int bRow = blockIdx.x * 64;
    int z = blockIdx.y;
    const float* W = z ? Wkt : Wks;

    float c[2][4][4];
#pragma unroll
    for (int mt = 0; mt < 2; ++mt)
#pragma unroll
        for (int nt = 0; nt < 4; ++nt)
#pragma unroll
            for (int j = 0; j < 4; ++j) c[mt][nt][j] = 0.f;

    for (int k0 = 0; k0 < 128; k0 += 32) {
#pragma unroll
        for (int i = 0; i < 2; ++i) {
            int idx = t + 256 * i;
            int row = idx >> 3, q = idx & 7;
            float4 v = *reinterpret_cast<const float4*>(
                &g_inputs[(size_t)(bRow + row) * 256 + z * 128 + k0 + q * 4]);
            As[row][q * 4 + 0] = __float_as_uint(v.x);
            As[row][q * 4 + 1] = __float_as_uint(v.y);
            As[row][q * 4 + 2] = __float_as_uint(v.z);
            As[row][q * 4 + 3] = __float_as_uint(v.w);
        }
#pragma unroll
        for (int i = 0; i < 4; ++i) {
            int idx = t + 256 * i;             // 0..1023
            int kk = idx >> 5, cq = idx & 31;
            float4 v = *reinterpret_cast<const float4*>(
                &W[(size_t)(k0 + kk) * 128 + cq * 4]);
            Bs2[kk][cq * 4 + 0] = __float_as_uint(v.x);
            Bs2[kk][cq * 4 + 1] = __float_as_uint(v.y);
            Bs2[kk][cq * 4 + 2] = __float_as_uint(v.z);
            Bs2[kk][cq * 4 + 3] = __float_as_uint(v.w);
        }
        __syncthreads();
#pragma unroll
        for (int ks = 0; ks < 4; ++ks) {
            uint32_t a[2][4];
#pragma unroll
            for (int mt = 0; mt < 2; ++mt) {
                int r = wr * 32 + mt * 16 + g;
                a[mt][0] = As[r][ks * 8 + tg];
                a[mt][1] = As[r + 8][ks * 8 + tg];
                a[mt][2] = As[r][ks * 8 + tg + 4];
                a[mt][3] = As[r + 8][ks * 8 + tg + 4];
            }
#pragma unroll
            for (int nt = 0; nt < 4; ++nt) {
                int cb = wc * 32 + nt * 8 + g;
                uint32_t b0 = Bs2[ks * 8 + tg][cb];
                uint32_t b1 = Bs2[ks * 8 + tg + 4][cb];
                mma_tf32(c[0][nt], a[0], b0, b1);
                mma_tf32(c[1][nt], a[1], b0, b1);
            }
        }
        __syncthreads();
    }
#pragma unroll
    for (int mt = 0; mt < 2; ++mt)
#pragma unroll
        for (int nt = 0; nt < 4; ++nt)
#pragma unroll
            for (int h = 0; h < 2; ++h) {
                int rl = wr * 32 + mt * 16 + h * 8 + g;
                size_t row = (size_t)(bRow + rl);
                int cb = wc * 32 + nt * 8 + tg * 2;
                float2 o;
                o.x = c[mt][nt][h * 2];
                o.y = c[mt][nt][h * 2 + 1];
                *reinterpret_cast<float2*>(&g_kcat[row * 256 + z * 128 + cb]) = o;
            }
}

// ------------------------- 5) q projection (scales prefolded) --------------
__global__ void qproj_kernel(const float* __restrict__ Wqs,
                             const float* __restrict__ Wqt) {
    __shared__ float s_slot[256];
    int t = threadIdx.x;
    int b = blockIdx.x, ks = blockIdx.y;
    s_slot[t] = g_slots[(b * KSL + ks) * 256 + t];
    __syncthreads();
    int half = t >> 7;
    int cc   = t & 127;
    const float* W = half ? Wqt : Wqs;
    const float rs = 0.08838834764831845f;    // 128^-0.5
    float sc = half ? 0.3f * rs : 0.7f * rs;
    float acc = 0.f;
    const float* sp = &s_slot[half * 128];
#pragma unroll 8
    for (int j = 0; j < 128; ++j) acc += sp[j] * W[j * 128 + cc];
    g_qcat[(b * KSL + ks) * 256 + t] = acc * sc;
}

// ------------------------- 6) logits + softmax(K) + rowsum partials --------
__global__ void __launch_bounds__(256)
logits_softmax_kernel() {
    __shared__ float s_q[8 * 256];
    __shared__ float s_k[32 * 260];
    __shared__ float s_m[32], s_e[32];
    __shared__ float s_a[8][32];
    int t  = threadIdx.x;
    int nc = blockIdx.x, b = blockIdx.y;

#pragma unroll
    for (int i = 0; i < 8; ++i) s_q[t + 256 * i] = g_qcat[b * 2048 + t + 256 * i];
#pragma unroll
    for (int i = 0; i < 8; ++i) {
        int idx = t + 256 * i;                  // float4 units, 0..2047
        int n = idx >> 6, dq = idx & 63;
        float4 v = *reinterpret_cast<const float4*>(
            &g_kcat[(size_t)(b * Nn + nc * 32 + n) * 256 + dq * 4]);
        *reinterpret_cast<float4*>(&s_k[n * 260 + dq * 4]) = v;
    }
    __syncthreads();

    int kk = t >> 5, nl = t & 31;
    const float4* q4 = reinterpret_cast<const float4*>(&s_q[kk * 256]);
    const float4* k4 = reinterpret_cast<const float4*>(&s_k[nl * 260]);
    float acc = 0.f;
#pragma unroll 8
    for (int d = 0; d < 64; ++d) {
        float4 qv = q4[d], kv = k4[d];
        acc += qv.x * kv.x + qv.y * kv.y + qv.z * kv.z + qv.w * kv.w;
    }
    s_a[kk][nl] = acc;
    __syncthreads();

    if (kk == 0) {
        float m = -1e30f;
#pragma unroll
        for (int i = 0; i < 8; ++i) m = fmaxf(m, s_a[i][nl]);
        float e = 0.f;
#pragma unroll
        for (int i = 0; i < 8; ++i) e += expf(s_a[i][nl] - m);
        s_m[nl] = m; s_e[nl] = e;
    }
    __syncthreads();

    float a = expf(acc - s_m[nl]) / s_e[nl];
    g_attn[(size_t)(b * KSL + kk) * Nn + nc * 32 + nl] = a;
    s_a[kk][nl] = a;
    __syncthreads();

    if (nl == 0) {
        float s = 0.f;
#pragma unroll
        for (int i = 0; i < 32; ++i) s += s_a[kk][i];
        g_rowsum_part[(b * KSL + kk) * 128 + nc] = s;
    }
}

// ------------------------- 7) updates stage 1 (partials over n) ------------
__global__ void __launch_bounds__(256)
upd1_kernel() {
    __shared__ float s_a[8][256];
    int t  = threadIdx.x;
    int nc = blockIdx.x, b = blockIdx.y;
#pragma unroll
    for (int i = 0; i < 8; ++i) {
        int idx = t + 256 * i;
        int kk = idx >> 8, nl = idx & 255;
        s_a[kk][nl] = g_attn[(size_t)(b * KSL + kk) * Nn + nc * 256 + nl];
    }
    __syncthreads();
    float acc[8] = {0, 0, 0, 0, 0, 0, 0, 0};
    const float* ip = &g_inputs[(size_t)(b * Nn + nc * 256) * 256 + t];
#pragma unroll 4
    for (int nl = 0; nl < 256; ++nl) {
        float inp = ip[(size_t)nl * 256];
#pragma unroll
        for (int kk = 0; kk < 8; ++kk) acc[kk] += s_a[kk][nl] * inp;
    }
#pragma unroll
    for (int kk = 0; kk < 8; ++kk)
        g_upd_part[((b * 16 + nc) * 8 + kk) * 256 + t] = acc[kk];
}

// ------------------------- 8) fused finalize + GRU + LN + MLP --------------
// 768 threads: one per gate column.
__global__ void __launch_bounds__(768)
gru_mlp_kernel(const float* __restrict__ W_ih, const float* __restrict__ W_hh,
               const float* __restrict__ b_ih, const float* __restrict__ b_hh,
               const float* __restrict__ lng, const float* __restrict__ lnb,
               const float* __restrict__ Wm1, const float* __restrict__ bm1,
               const float* __restrict__ Wm2, const float* __restrict__ bm2) {
    __shared__ float s_x[256], s_h[256], s_t2[512];
    __shared__ float s_gx[768], s_gh[768];
    __shared__ float wred[8], wred2[8];
    __shared__ float s_rs;
    int t  = threadIdx.x;
    int ks = blockIdx.x, b = blockIdx.y;
    int lane = t & 31, w = t >> 5;

    // rowsum reduce (128 partials) with warps 0..3
    float v = (t < 128) ? g_rowsum_part[(b * KSL + ks) * 128 + t] : 0.f;
#pragma unroll
    for (int o = 16; o > 0; o >>= 1) v += __shfl_xor_sync(0xffffffffu, v, o);
    if (lane == 0 && w < 4) wred[w] = v;
    __syncthreads();
    if (t == 0) s_rs = wred[0] + wred[1] + wred[2] + wred[3];
    __syncthreads();
    float inv_rs = 1.0f / (s_rs + 1e-8f);

    if (t < 256) {
        float u = 0.f;
#pragma unroll
        for (int ncp = 0; ncp < 16; ++ncp)
            u += g_upd_part[((b * 16 + ncp) * 8 + ks) * 256 + t];
        s_x[t] = u * inv_rs;
        s_h[t] = g_slots[(b * KSL + ks) * 256 + t];
    }
    __syncthreads();

    // gates: thread t computes gate column t (of 768)
    {
        float gx = b_ih[t], gh = b_hh[t];
#pragma unroll 4
        for (int m = 0; m < 256; ++m) {
            gx += s_x[m] * W_ih[m * 768 + t];
            gh += s_h[m] * W_hh[m * 768 + t];
        }
        s_gx[t] = gx;
        s_gh[t] = gh;
    }
    __syncthreads();

    float h = 0.f, hprev = 0.f;
    if (t < 256) {
        hprev = s_h[t];
        float r = sigmoidf_(s_gx[t] + s_gh[t]);
        float z = sigmoidf_(s_gx[t + 256] + s_gh[t + 256]);
        float n = tanhf(s_gx[t + 512] + r * s_gh[t + 512]);
        h = (1.0f - z) * n + z * hprev;
    }

    // LN over 256 (warps 0..7 hold the data)
    float s1 = h, s2 = h * h;
#pragma unroll
    for (int o = 16; o > 0; o >>= 1) {
        s1 += __shfl_xor_sync(0xffffffffu, s1, o);
        s2 += __shfl_xor_sync(0xffffffffu, s2, o);
    }
    if (lane == 0 && w < 8) { wred[w] = s1; wred2[w] = s2; }
    __syncthreads();
    if (t < 256) {
        float S = 0.f, S2 = 0.f;
#pragma unroll
        for (int i = 0; i < 8; ++i) { S += wred[i]; S2 += wred2[i]; }
        float mean = S * (1.0f / 256.0f);
        float var  = S2 * (1.0f / 256.0f) - mean * mean;
        float sn = (h - mean) * rsqrtf(var + 1e-5f) * lng[t] + lnb[t];
        s_x[t] = sn;
    }
    __syncthreads();

    // MLP layer 1: threads 0..511, one column each
    if (t < 512) {
        float m0 = bm1[t];
#pragma unroll 4
        for (int j = 0; j < 256; ++j) m0 += s_x[j] * Wm1[j * 512 + t];
        s_t2[t] = gelu_exact(m0);
    }
    __syncthreads();

    // MLP layer 2: threads 0..255
    if (t < 256) {
        float out = bm2[t];
#pragma unroll 4
        for (int j = 0; j < 512; ++j) out += s_t2[j] * Wm2[j * 256 + t];
        g_slots[(b * KSL + ks) * 256 + t] = h + out;
    }
}

// ------------------------- 9) pack outputs ---------------------------------
__global__ void writeout_kernel(float* __restrict__ out) {
    int i = blockIdx.x * 256 + threadIdx.x;   // < 1179648
    const int SZ_SLOTS = Bsz * KSL * DS;      // 65536
    const int SZ_ATTN  = Bsz * KSL * Nn;      // 1048576
    const int SZ_HALF  = Bsz * KSL * DH;      // 32768
    if (i < SZ_SLOTS) {
        out[i] = g_slots[i];
    } else if (i < SZ_SLOTS + SZ_ATTN) {
        out[i] = g_attn[i - SZ_SLOTS];
    } else if (i < SZ_SLOTS + SZ_ATTN + SZ_HALF) {
        int j = i - SZ_SLOTS - SZ_ATTN;
        int bk = j >> 7, d = j & 127;
        out[i] = g_slots[bk * 256 + d];
    } else if (i < SZ_SLOTS + SZ_ATTN + 2 * SZ_HALF) {
        int j = i - SZ_SLOTS - SZ_ATTN - SZ_HALF;
        int bk = j >> 7, d = j & 127;
        out[i] = g_slots[bk * 256 + 128 + d];
    }
}

// ------------------------- launch ------------------------------------------
extern "C" void kernel_launch(void* const* d_in, const int* in_sizes, int n_in,
                              void* d_out, int out_size) {
    const float* features = (const float*)d_in[0];
    const float* Wi1  = (const float*)d_in[1];
    const float* bi1  = (const float*)d_in[2];
    const float* Wi2  = (const float*)d_in[3];
    const float* bi2  = (const float*)d_in[4];
    const float* Wp   = (const float*)d_in[5];
    const float* bp   = (const float*)d_in[6];
    const float* ln_in_g = (const float*)d_in[7];
    const float* ln_in_b = (const float*)d_in[8];
    const float* Wqs  = (const float*)d_in[9];
    const float* Wks  = (const float*)d_in[10];
    const float* Wqt  = (const float*)d_in[11];
    const float* Wkt  = (const float*)d_in[12];
    const float* W_ih = (const float*)d_in[13];
    const float* W_hh = (const float*)d_in[14];
    const float* b_ih = (const float*)d_in[15];
    const float* b_hh = (const float*)d_in[16];
    const float* ln_g = (const float*)d_in[17];
    const float* ln_b = (const float*)d_in[18];
    const float* Wm1  = (const float*)d_in[19];
    const float* bm1  = (const float*)d_in[20];
    const float* Wm2  = (const float*)d_in[21];
    const float* bm2  = (const float*)d_in[22];
    float* out = (float*)d_out;

    cudaFuncSetAttribute(gemm_ln_tc, cudaFuncAttributeMaxDynamicSharedMemorySize,
                         GL_SMEM_BYTES);

    pool_part_kernel<<<dim3(3, 8, 32), 256>>>(features);
    pool_reduce_kernel<<<dim3(3, 32), 256>>>();
    slots_init1_kernel<<<dim3(2, 32), 256>>>(Wi1, bi1);
    slots_init2_kernel<<<dim3(8, 32), 256>>>(Wi2, bi2);
    gemm_ln_tc<<<1024, 512, GL_SMEM_BYTES>>>(features, Wp, bp, ln_in_g, ln_in_b);
    kproj_tc<<<dim3(2048, 2), 256>>>(Wks, Wkt);

    for (int it = 0; it < NITER; ++it) {
        qproj_kernel<<<dim3(32, 8), 256>>>(Wqs, Wqt);
        logits_softmax_kernel<<<dim3(128, 32), 256>>>();
        upd1_kernel<<<dim3(16, 32), 256>>>();
        gru_mlp_kernel<<<dim3(8, 32), 768>>>(W_ih, W_hh, b_ih, b_hh,
                                             ln_g, ln_b, Wm1, bm1, Wm2, bm2);
    }
    writeout_kernel<<<4608, 256>>>(out);
}